// round 1
// baseline (speedup 1.0000x reference)
#include <cuda_runtime.h>
#include <cuda_bf16.h>

// Problem constants
#define BATCH 8
#define SEQ   2048
#define EMBD  1024
#define OUTD  1024

// Scratch: c = Linear(embd)  [8,2048,1024] fp32, s = scores [8,2048,2048] fp32
__device__ float g_c[(size_t)BATCH * SEQ * OUTD];        // 64 MB
__device__ float g_s[(size_t)BATCH * SEQ * SEQ];         // 128 MB

// ---------------------------------------------------------------------------
// Tiled SGEMM: C = alpha * A @ op(B) (+ bias)
//   A: [M,K] row-major.
//   BNT=true : B is [N,K] row-major (NT gemm, both K-contiguous)
//   BNT=false: B is [K,N] row-major (NN gemm)
// Block tile 128x128xK8, 256 threads, 8x8 per-thread micro-tile.
// Requires M%128==0, N%128==0, K%8==0 (all shapes here satisfy this).
// ---------------------------------------------------------------------------
#define BM 128
#define BN 128
#define BK 8
#define TM 8
#define TN 8

template <bool BNT, bool BIAS>
__global__ __launch_bounds__(256)
void sgemm_kernel(const float* __restrict__ A, const float* __restrict__ B,
                  const float* __restrict__ bias, float* __restrict__ C,
                  int M, int N, int K, float alpha,
                  size_t strideA, size_t strideB, size_t strideC)
{
    A += (size_t)blockIdx.z * strideA;
    B += (size_t)blockIdx.z * strideB;
    C += (size_t)blockIdx.z * strideC;

    __shared__ float As[BK][BM];
    __shared__ float Bs[BK][BN];

    const int tid  = threadIdx.x;
    const int row0 = blockIdx.y * BM;
    const int col0 = blockIdx.x * BN;

    // A tile load mapping: 128 rows x 8 cols, each thread 1 float4 along K
    const int a_r = tid >> 1;            // 0..127
    const int a_c = (tid & 1) * 4;       // 0 or 4
    // B NN load mapping: 8 rows(K) x 128 cols, each thread 1 float4 along N
    const int bn_k = tid >> 5;           // 0..7
    const int bn_n = (tid & 31) * 4;     // 0..124

    const int tx = tid & 15;             // 0..15  -> col micro-tile
    const int ty = tid >> 4;             // 0..15  -> row micro-tile

    float acc[TM][TN];
#pragma unroll
    for (int i = 0; i < TM; i++)
#pragma unroll
        for (int j = 0; j < TN; j++) acc[i][j] = 0.f;

    for (int k0 = 0; k0 < K; k0 += BK) {
        // --- stage A (transposed into As[k][m]) ---
        {
            float4 av = *reinterpret_cast<const float4*>(
                A + (size_t)(row0 + a_r) * K + k0 + a_c);
            As[a_c + 0][a_r] = av.x;
            As[a_c + 1][a_r] = av.y;
            As[a_c + 2][a_r] = av.z;
            As[a_c + 3][a_r] = av.w;
        }
        // --- stage B ---
        if (BNT) {
            float4 bv = *reinterpret_cast<const float4*>(
                B + (size_t)(col0 + a_r) * K + k0 + a_c);
            Bs[a_c + 0][a_r] = bv.x;
            Bs[a_c + 1][a_r] = bv.y;
            Bs[a_c + 2][a_r] = bv.z;
            Bs[a_c + 3][a_r] = bv.w;
        } else {
            float4 bv = *reinterpret_cast<const float4*>(
                B + (size_t)(k0 + bn_k) * N + col0 + bn_n);
            *reinterpret_cast<float4*>(&Bs[bn_k][bn_n]) = bv;
        }
        __syncthreads();

#pragma unroll
        for (int k = 0; k < BK; k++) {
            float4 a0 = *reinterpret_cast<const float4*>(&As[k][ty * TM]);
            float4 a1 = *reinterpret_cast<const float4*>(&As[k][ty * TM + 4]);
            float4 b0 = *reinterpret_cast<const float4*>(&Bs[k][tx * TN]);
            float4 b1 = *reinterpret_cast<const float4*>(&Bs[k][tx * TN + 4]);
            float af[TM] = {a0.x, a0.y, a0.z, a0.w, a1.x, a1.y, a1.z, a1.w};
            float bf[TN] = {b0.x, b0.y, b0.z, b0.w, b1.x, b1.y, b1.z, b1.w};
#pragma unroll
            for (int i = 0; i < TM; i++)
#pragma unroll
                for (int j = 0; j < TN; j++)
                    acc[i][j] = fmaf(af[i], bf[j], acc[i][j]);
        }
        __syncthreads();
    }

    // epilogue
#pragma unroll
    for (int i = 0; i < TM; i++) {
        const size_t r = (size_t)(row0 + ty * TM + i);
#pragma unroll
        for (int j = 0; j < TN; j += 4) {
            const int c = col0 + tx * TN + j;
            float4 v;
            v.x = acc[i][j + 0] * alpha;
            v.y = acc[i][j + 1] * alpha;
            v.z = acc[i][j + 2] * alpha;
            v.w = acc[i][j + 3] * alpha;
            if (BIAS) {
                v.x += bias[c + 0];
                v.y += bias[c + 1];
                v.z += bias[c + 2];
                v.w += bias[c + 3];
            }
            *reinterpret_cast<float4*>(C + r * N + c) = v;
        }
    }
}

// ---------------------------------------------------------------------------
// Row softmax over 2048 columns. One block (256 threads) per row; the 8
// values per thread stay in registers across max/exp/sum/normalize.
// ---------------------------------------------------------------------------
__global__ __launch_bounds__(256)
void softmax_kernel(float* __restrict__ S)
{
    const int COLS = SEQ;                 // 2048
    float* p = S + (size_t)blockIdx.x * COLS;
    const int tid  = threadIdx.x;
    const int lane = tid & 31;
    const int wid  = tid >> 5;

    __shared__ float red[8];

    float v[8];
    float m = -1e30f;
#pragma unroll
    for (int k = 0; k < 8; k++) {
        v[k] = p[tid + k * 256];
        m = fmaxf(m, v[k]);
    }
#pragma unroll
    for (int o = 16; o > 0; o >>= 1)
        m = fmaxf(m, __shfl_xor_sync(0xffffffffu, m, o));
    if (lane == 0) red[wid] = m;
    __syncthreads();
    float bm = red[0];
#pragma unroll
    for (int i = 1; i < 8; i++) bm = fmaxf(bm, red[i]);
    __syncthreads();

    float s = 0.f;
#pragma unroll
    for (int k = 0; k < 8; k++) {
        v[k] = __expf(v[k] - bm);
        s += v[k];
    }
#pragma unroll
    for (int o = 16; o > 0; o >>= 1)
        s += __shfl_xor_sync(0xffffffffu, s, o);
    if (lane == 0) red[wid] = s;
    __syncthreads();
    float total = 0.f;
#pragma unroll
    for (int i = 0; i < 8; i++) total += red[i];
    const float inv = 1.f / total;

#pragma unroll
    for (int k = 0; k < 8; k++)
        p[tid + k * 256] = v[k] * inv;
}

// ---------------------------------------------------------------------------
extern "C" void kernel_launch(void* const* d_in, const int* in_sizes, int n_in,
                              void* d_out, int out_size)
{
    const float* embd = (const float*)d_in[0];   // [8,2048,1024]
    const float* W    = (const float*)d_in[1];   // [1024,1024] (out,in)
    const float* bias = (const float*)d_in[2];   // [1024]
    float* out = (float*)d_out;                  // [8,2048,1024]

    float* c_ptr = nullptr;
    float* s_ptr = nullptr;
    cudaGetSymbolAddress((void**)&c_ptr, g_c);
    cudaGetSymbolAddress((void**)&s_ptr, g_s);

    const float scale = 0.03125f;  // 1/sqrt(1024)

    // 1) c = embd @ W^T + b   (M=16384, N=1024, K=1024, NT)
    {
        dim3 grid(OUTD / BN, (BATCH * SEQ) / BM, 1);
        sgemm_kernel<true, true><<<grid, 256>>>(
            embd, W, bias, c_ptr,
            BATCH * SEQ, OUTD, EMBD, 1.0f,
            0, 0, 0);
    }

    // 2) s = (c @ c^T) * scale per batch  (M=2048, N=2048, K=1024, NT)
    {
        dim3 grid(SEQ / BN, SEQ / BM, BATCH);
        sgemm_kernel<true, false><<<grid, 256>>>(
            c_ptr, c_ptr, nullptr, s_ptr,
            SEQ, SEQ, OUTD, scale,
            (size_t)SEQ * OUTD, (size_t)SEQ * OUTD, (size_t)SEQ * SEQ);
    }

    // 3) softmax rows of s
    softmax_kernel<<<BATCH * SEQ, 256>>>(s_ptr);

    // 4) out = s @ c per batch  (M=2048, N=1024, K=2048, NN)
    {
        dim3 grid(OUTD / BN, SEQ / BM, BATCH);
        sgemm_kernel<false, false><<<grid, 256>>>(
            s_ptr, c_ptr, nullptr, out,
            SEQ, OUTD, SEQ, 1.0f,
            (size_t)SEQ * SEQ, (size_t)SEQ * OUTD, (size_t)SEQ * OUTD);
    }
}

// round 3
// speedup vs baseline: 2.1330x; 2.1330x over previous
#include <cuda_runtime.h>
#include <cuda_bf16.h>
#include <cstdint>

#define BATCH 8
#define SEQ   2048
#define EMBD  1024
#define OUTD  1024

// Scratch (device globals; allocations are forbidden)
__device__ __align__(256) float g_et[(size_t)BATCH * SEQ * EMBD];  // tf32 embd  64MB
__device__ __align__(256) float g_wt[(size_t)OUTD * EMBD];         // tf32 W      4MB
__device__ __align__(256) float g_c [(size_t)BATCH * SEQ * OUTD];  // c (tf32)   64MB
__device__ __align__(256) float g_s [(size_t)BATCH * SEQ * SEQ];   // scores    128MB

// ---------------------------------------------------------------------------
__device__ __forceinline__ uint32_t smem_u32(const void* p) {
    uint32_t a;
    asm("{ .reg .u64 t; cvta.to.shared.u64 t, %1; cvt.u32.u64 %0, t; }"
        : "=r"(a) : "l"(p));
    return a;
}
// fp32 -> tf32 round-to-nearest (unbiased)
__device__ __forceinline__ float rtf(float x) {
    uint32_t u;
    asm("cvt.rna.tf32.f32 %0, %1;" : "=r"(u) : "f"(x));
    return __uint_as_float(u);
}
__device__ __forceinline__ uint32_t lds_u(uint32_t a) {
    uint32_t v;
    asm volatile("ld.shared.b32 %0, [%1];" : "=r"(v) : "r"(a));
    return v;
}
__device__ __forceinline__ void mma_tf32(float c[4], uint32_t a0, uint32_t a1,
                                         uint32_t a2, uint32_t a3,
                                         uint32_t b0, uint32_t b1) {
    asm volatile(
        "mma.sync.aligned.m16n8k8.row.col.f32.tf32.tf32.f32 "
        "{%0,%1,%2,%3}, {%4,%5,%6,%7}, {%8,%9}, {%0,%1,%2,%3};"
        : "+f"(c[0]), "+f"(c[1]), "+f"(c[2]), "+f"(c[3])
        : "r"(a0), "r"(a1), "r"(a2), "r"(a3), "r"(b0), "r"(b1));
}
__device__ __forceinline__ uint32_t sw128(uint32_t bo) {
    return bo ^ ((bo >> 3) & 0x70);
}

// ---------------------------------------------------------------------------
// tf32 mma.sync GEMM: 128x128 CTA tile, BK=32, 8 warps (2m x 4n), warp 64x32.
// MODE 0: NT, epilogue = +bias, round->tf32   (GEMM1: c = embd@W^T + b)
// MODE 1: NT, epilogue = *alpha               (GEMM2: logits)
// MODE 2: NN, plain                            (GEMM3: out = P@c)
// ---------------------------------------------------------------------------
#define STG     3
#define A_TB    16384                    // 128 rows x 128B
#define SB_OFF  (STG * A_TB)             // 49152
#define B_TB_NT 16384
#define B_PITCH 544                      // NN: 136 floats/row (conflict-free)
#define B_TB_NN (32 * B_PITCH)           // 17408
#define DSMEM_NT (SB_OFF + STG * B_TB_NT + 1024)
#define DSMEM_NN (SB_OFF + STG * B_TB_NN + 1024)

template <int MODE>
__global__ __launch_bounds__(256, 2)
void tc_gemm(const float* __restrict__ Ag, const float* __restrict__ Bg,
             const float* __restrict__ bias, float* __restrict__ Cg,
             int N, int K, float alpha,
             size_t strA, size_t strB, size_t strC)
{
    constexpr bool BNT = (MODE != 2);
    constexpr int  B_TB = BNT ? B_TB_NT : B_TB_NN;

    extern __shared__ char dsm[];
    const uint32_t sb = (smem_u32(dsm) + 1023u) & ~1023u;

    Ag += (size_t)blockIdx.z * strA;
    Bg += (size_t)blockIdx.z * strB;
    Cg += (size_t)blockIdx.z * strC;

    const int tid  = threadIdx.x;
    const int lane = tid & 31;
    const int wid  = tid >> 5;
    const int wm0  = (wid & 1) * 64;     // warp m offset in tile
    const int wn0  = (wid >> 1) * 32;    // warp n offset in tile
    const int row0 = blockIdx.y * 128;
    const int col0 = blockIdx.x * 128;

    const int NCH = K >> 5;

    float acc[4][4][4];
#pragma unroll
    for (int i = 0; i < 4; i++)
#pragma unroll
        for (int j = 0; j < 4; j++)
#pragma unroll
            for (int r = 0; r < 4; r++) acc[i][j][r] = 0.f;

    auto issue = [&](int ch) {
        const int st = ch % STG;
        const int k0 = ch << 5;
#pragma unroll
        for (int i = 0; i < 8; i++) {
            int g   = tid + (i << 8);          // 0..2047
            int isB = g >> 10;
            int gl  = g & 1023;
            const float* src;
            uint32_t dst;
            if (!isB) {                        // A: 128 rows x 8 granules
                int r  = gl >> 3;
                int gg = gl & 7;
                src = Ag + (size_t)(row0 + r) * K + k0 + (gg << 2);
                dst = sb + st * A_TB + sw128((r << 7) + (gg << 4));
            } else if (BNT) {                  // B NT: [n][k], 128 rows x 8 gran
                int r  = gl >> 3;
                int gg = gl & 7;
                src = Bg + (size_t)(col0 + r) * K + k0 + (gg << 2);
                dst = sb + SB_OFF + st * B_TB + sw128((r << 7) + (gg << 4));
            } else {                           // B NN: [k][n], 32 rows x 32 gran
                int kr = gl >> 5;
                int gg = gl & 31;
                src = Bg + (size_t)(k0 + kr) * N + col0 + (gg << 2);
                dst = sb + SB_OFF + st * B_TB + kr * B_PITCH + (gg << 4);
            }
            asm volatile("cp.async.cg.shared.global [%0], [%1], 16;"
                         :: "r"(dst), "l"(src) : "memory");
        }
        asm volatile("cp.async.commit_group;" ::: "memory");
    };

    issue(0);
    issue(1);

    for (int ch = 0; ch < NCH; ch++) {
        asm volatile("cp.async.wait_group 1;" ::: "memory");
        __syncthreads();
        if (ch + 2 < NCH) issue(ch + 2);
        else asm volatile("cp.async.commit_group;" ::: "memory");

        const int st = ch % STG;
        const uint32_t ab = sb + st * A_TB;
        const uint32_t bb = sb + SB_OFF + st * B_TB;
        const int q = lane >> 2;               // 0..7
        const int s = lane & 3;                // 0..3

#pragma unroll
        for (int ks = 0; ks < 4; ks++) {
            const int k0 = ks << 3;
            uint32_t bf[4][2];
#pragma unroll
            for (int tn = 0; tn < 4; tn++) {
                const int n = wn0 + (tn << 3) + q;
                if (BNT) {
                    bf[tn][0] = lds_u(bb + sw128((n << 7) + ((k0 + s) << 2)));
                    bf[tn][1] = lds_u(bb + sw128((n << 7) + ((k0 + s + 4) << 2)));
                } else {
                    bf[tn][0] = lds_u(bb + (k0 + s) * B_PITCH + (n << 2));
                    bf[tn][1] = lds_u(bb + (k0 + s + 4) * B_PITCH + (n << 2));
                }
            }
#pragma unroll
            for (int tm = 0; tm < 4; tm++) {
                const int r = wm0 + (tm << 4) + q;
                uint32_t a0 = lds_u(ab + sw128((r << 7) + ((k0 + s) << 2)));
                uint32_t a1 = lds_u(ab + sw128(((r + 8) << 7) + ((k0 + s) << 2)));
                uint32_t a2 = lds_u(ab + sw128((r << 7) + ((k0 + s + 4) << 2)));
                uint32_t a3 = lds_u(ab + sw128(((r + 8) << 7) + ((k0 + s + 4) << 2)));
#pragma unroll
                for (int tn = 0; tn < 4; tn++)
                    mma_tf32(acc[tm][tn], a0, a1, a2, a3, bf[tn][0], bf[tn][1]);
            }
        }
        __syncthreads();
    }

    // -------- epilogue --------
    const int q = lane >> 2;
    const int s = lane & 3;
#pragma unroll
    for (int tm = 0; tm < 4; tm++) {
        const size_t r_lo = (size_t)row0 + wm0 + (tm << 4) + q;
#pragma unroll
        for (int tn = 0; tn < 4; tn++) {
            const int col = col0 + wn0 + (tn << 3) + (s << 1);
            float v0 = acc[tm][tn][0], v1 = acc[tm][tn][1];
            float v2 = acc[tm][tn][2], v3 = acc[tm][tn][3];
            if (MODE == 0) {
                const float b0 = __ldg(bias + col), b1 = __ldg(bias + col + 1);
                v0 = rtf(v0 + b0); v1 = rtf(v1 + b1);
                v2 = rtf(v2 + b0); v3 = rtf(v3 + b1);
            } else if (MODE == 1) {
                v0 *= alpha; v1 *= alpha; v2 *= alpha; v3 *= alpha;
            }
            *reinterpret_cast<float2*>(Cg + r_lo * N + col)       = make_float2(v0, v1);
            *reinterpret_cast<float2*>(Cg + (r_lo + 8) * N + col) = make_float2(v2, v3);
        }
    }
}

// ---------------------------------------------------------------------------
__global__ __launch_bounds__(256)
void round_k(const float4* __restrict__ in, float4* __restrict__ out, int n4)
{
    int i = blockIdx.x * 256 + threadIdx.x;
    if (i < n4) {
        float4 v = in[i];
        v.x = rtf(v.x); v.y = rtf(v.y); v.z = rtf(v.z); v.w = rtf(v.w);
        out[i] = v;
    }
}

// row softmax over 2048 cols; probs rounded to tf32 for GEMM3
__global__ __launch_bounds__(256)
void softmax_kernel(float* __restrict__ S)
{
    float* p = S + (size_t)blockIdx.x * SEQ;
    const int tid  = threadIdx.x;
    const int lane = tid & 31;
    const int wid  = tid >> 5;
    __shared__ float red[8];

    float v[8];
    float m = -1e30f;
#pragma unroll
    for (int k = 0; k < 8; k++) {
        v[k] = p[tid + k * 256];
        m = fmaxf(m, v[k]);
    }
#pragma unroll
    for (int o = 16; o > 0; o >>= 1)
        m = fmaxf(m, __shfl_xor_sync(0xffffffffu, m, o));
    if (lane == 0) red[wid] = m;
    __syncthreads();
    float bm = red[0];
#pragma unroll
    for (int i = 1; i < 8; i++) bm = fmaxf(bm, red[i]);
    __syncthreads();

    float sum = 0.f;
#pragma unroll
    for (int k = 0; k < 8; k++) {
        v[k] = __expf(v[k] - bm);
        sum += v[k];
    }
#pragma unroll
    for (int o = 16; o > 0; o >>= 1)
        sum += __shfl_xor_sync(0xffffffffu, sum, o);
    if (lane == 0) red[wid] = sum;
    __syncthreads();
    float total = 0.f;
#pragma unroll
    for (int i = 0; i < 8; i++) total += red[i];
    const float inv = 1.f / total;

#pragma unroll
    for (int k = 0; k < 8; k++)
        p[tid + k * 256] = rtf(v[k] * inv);
}

// ---------------------------------------------------------------------------
extern "C" void kernel_launch(void* const* d_in, const int* in_sizes, int n_in,
                              void* d_out, int out_size)
{
    const float* embd = (const float*)d_in[0];   // [8,2048,1024]
    const float* W    = (const float*)d_in[1];   // [1024,1024]
    const float* bias = (const float*)d_in[2];   // [1024]
    float* out = (float*)d_out;                  // [8,2048,1024]

    float *et, *wt, *c, *s;
    cudaGetSymbolAddress((void**)&et, g_et);
    cudaGetSymbolAddress((void**)&wt, g_wt);
    cudaGetSymbolAddress((void**)&c,  g_c);
    cudaGetSymbolAddress((void**)&s,  g_s);

    cudaFuncSetAttribute(tc_gemm<0>, cudaFuncAttributeMaxDynamicSharedMemorySize, DSMEM_NT);
    cudaFuncSetAttribute(tc_gemm<1>, cudaFuncAttributeMaxDynamicSharedMemorySize, DSMEM_NT);
    cudaFuncSetAttribute(tc_gemm<2>, cudaFuncAttributeMaxDynamicSharedMemorySize, DSMEM_NN);

    const float scale = 0.03125f;  // 1/sqrt(1024)

    // prepass: round inputs to tf32 (unbiased)
    {
        int n4e = BATCH * SEQ * EMBD / 4;
        round_k<<<n4e / 256, 256>>>((const float4*)embd, (float4*)et, n4e);
        int n4w = OUTD * EMBD / 4;
        round_k<<<n4w / 256, 256>>>((const float4*)W, (float4*)wt, n4w);
    }

    // 1) c = embd @ W^T + b  (NT, M=16384, N=1024, K=1024), c rounded to tf32
    {
        dim3 grid(OUTD / 128, (BATCH * SEQ) / 128, 1);
        tc_gemm<0><<<grid, 256, DSMEM_NT>>>(et, wt, bias, c,
                                            OUTD, EMBD, 1.0f, 0, 0, 0);
    }
    // 2) s = (c @ c^T) * scale per batch  (NT, M=N=2048, K=1024)
    {
        dim3 grid(SEQ / 128, SEQ / 128, BATCH);
        tc_gemm<1><<<grid, 256, DSMEM_NT>>>(c, c, nullptr, s,
                                            SEQ, OUTD, scale,
                                            (size_t)SEQ * OUTD, (size_t)SEQ * OUTD,
                                            (size_t)SEQ * SEQ);
    }
    // 3) softmax rows (stores tf32-rounded probs)
    softmax_kernel<<<BATCH * SEQ, 256>>>(s);

    // 4) out = P @ c  (NN, M=2048, N=1024, K=2048)
    {
        dim3 grid(OUTD / 128, SEQ / 128, BATCH);
        tc_gemm<2><<<grid, 256, DSMEM_NN>>>(s, c, nullptr, out,
                                            OUTD, SEQ, 1.0f,
                                            (size_t)SEQ * SEQ, (size_t)SEQ * OUTD,
                                            (size_t)SEQ * OUTD);
    }
}

// round 4
// speedup vs baseline: 2.4741x; 1.1599x over previous
#include <cuda_runtime.h>
#include <cuda_bf16.h>
#include <cstdint>

#define BATCH 8
#define SEQ   2048
#define EMBD  1024
#define OUTD  1024

// Scratch (device globals; allocations are forbidden)
__device__ __align__(256) float g_et[(size_t)BATCH * SEQ * EMBD];  // tf32 embd  64MB
__device__ __align__(256) float g_wt[(size_t)OUTD * EMBD];         // tf32 W      4MB
__device__ __align__(256) float g_c [(size_t)BATCH * SEQ * OUTD];  // c (tf32)   64MB
__device__ __align__(256) float g_s [(size_t)BATCH * SEQ * SEQ];   // scores    128MB

// ---------------------------------------------------------------------------
__device__ __forceinline__ uint32_t smem_u32(const void* p) {
    uint32_t a;
    asm("{ .reg .u64 t; cvta.to.shared.u64 t, %1; cvt.u32.u64 %0, t; }"
        : "=r"(a) : "l"(p));
    return a;
}
// fp32 -> tf32 round-to-nearest (unbiased)
__device__ __forceinline__ float rtf(float x) {
    uint32_t u;
    asm("cvt.rna.tf32.f32 %0, %1;" : "=r"(u) : "f"(x));
    return __uint_as_float(u);
}
__device__ __forceinline__ uint32_t lds_u(uint32_t a) {
    uint32_t v;
    asm volatile("ld.shared.b32 %0, [%1];" : "=r"(v) : "r"(a));
    return v;
}
__device__ __forceinline__ void sts_f(uint32_t a, float v) {
    asm volatile("st.shared.b32 [%0], %1;" :: "r"(a), "f"(v) : "memory");
}
__device__ __forceinline__ float4 lds_f4(uint32_t a) {
    float4 v;
    asm volatile("ld.shared.v4.f32 {%0,%1,%2,%3}, [%4];"
                 : "=f"(v.x), "=f"(v.y), "=f"(v.z), "=f"(v.w) : "r"(a));
    return v;
}
__device__ __forceinline__ void mma_tf32(float c[4], uint32_t a0, uint32_t a1,
                                         uint32_t a2, uint32_t a3,
                                         uint32_t b0, uint32_t b1) {
    asm volatile(
        "mma.sync.aligned.m16n8k8.row.col.f32.tf32.tf32.f32 "
        "{%0,%1,%2,%3}, {%4,%5,%6,%7}, {%8,%9}, {%0,%1,%2,%3};"
        : "+f"(c[0]), "+f"(c[1]), "+f"(c[2]), "+f"(c[3])
        : "r"(a0), "r"(a1), "r"(a2), "r"(a3), "r"(b0), "r"(b1));
}
__device__ __forceinline__ uint32_t sw128(uint32_t bo) {
    return bo ^ ((bo >> 3) & 0x70);
}

// ---------------------------------------------------------------------------
// tf32 mma.sync GEMM: 128x128 CTA tile, BK=32, 8 warps (2m x 4n), warp 64x32.
// MODE 0: NT, epilogue = +bias, round->tf32      (GEMM1: c = embd@W^T + b)
// MODE 2: NN, plain                              (GEMM3: out = P@c)
// MODE 3: NT, *alpha, SYMMETRIC triangular tiles (GEMM2: logits, mirrored)
// ---------------------------------------------------------------------------
#define STG     3
#define A_TB    16384                    // 128 rows x 128B
#define SB_OFF  (STG * A_TB)             // 49152
#define B_TB_NT 16384
#define B_PITCH 544                      // NN: 136 floats/row (conflict-free)
#define B_TB_NN (32 * B_PITCH)           // 17408
#define DSMEM_NT (SB_OFF + STG * B_TB_NT + 1024)
#define DSMEM_NN (SB_OFF + STG * B_TB_NN + 1024)
#define TPITCH  132                      // transpose staging pitch (floats)

template <int MODE>
__global__ __launch_bounds__(256, 2)
void tc_gemm(const float* __restrict__ Ag, const float* __restrict__ Bg,
             const float* __restrict__ bias, float* __restrict__ Cg,
             int N, int K, float alpha,
             size_t strA, size_t strB, size_t strC)
{
    constexpr bool BNT = (MODE != 2);
    constexpr int  B_TB = BNT ? B_TB_NT : B_TB_NN;

    extern __shared__ char dsm[];
    const uint32_t sb = (smem_u32(dsm) + 1023u) & ~1023u;

    Ag += (size_t)blockIdx.z * strA;
    Bg += (size_t)blockIdx.z * strB;
    Cg += (size_t)blockIdx.z * strC;

    const int tid  = threadIdx.x;
    const int lane = tid & 31;
    const int wid  = tid >> 5;
    const int wm0  = (wid & 1) * 64;     // warp m offset in tile
    const int wn0  = (wid >> 1) * 32;    // warp n offset in tile

    int row0, col0;
    if (MODE == 3) {
        // triangular tile decode: t -> (r, c) with c <= r
        const int t = blockIdx.x;
        int r = (int)((sqrtf(8.0f * (float)t + 1.0f) - 1.0f) * 0.5f);
        while ((r + 1) * (r + 2) / 2 <= t) r++;
        while (r * (r + 1) / 2 > t)        r--;
        const int cc = t - r * (r + 1) / 2;
        row0 = r  * 128;
        col0 = cc * 128;
    } else {
        row0 = blockIdx.y * 128;
        col0 = blockIdx.x * 128;
    }

    const int NCH = K >> 5;

    float acc[4][4][4];
#pragma unroll
    for (int i = 0; i < 4; i++)
#pragma unroll
        for (int j = 0; j < 4; j++)
#pragma unroll
            for (int r = 0; r < 4; r++) acc[i][j][r] = 0.f;

    auto issue = [&](int ch) {
        const int st = ch % STG;
        const int k0 = ch << 5;
#pragma unroll
        for (int i = 0; i < 8; i++) {
            int g   = tid + (i << 8);          // 0..2047
            int isB = g >> 10;
            int gl  = g & 1023;
            const float* src;
            uint32_t dst;
            if (!isB) {                        // A: 128 rows x 8 granules
                int r  = gl >> 3;
                int gg = gl & 7;
                src = Ag + (size_t)(row0 + r) * K + k0 + (gg << 2);
                dst = sb + st * A_TB + sw128((r << 7) + (gg << 4));
            } else if (BNT) {                  // B NT: [n][k], 128 rows x 8 gran
                int r  = gl >> 3;
                int gg = gl & 7;
                src = Bg + (size_t)(col0 + r) * K + k0 + (gg << 2);
                dst = sb + SB_OFF + st * B_TB + sw128((r << 7) + (gg << 4));
            } else {                           // B NN: [k][n], 32 rows x 32 gran
                int kr = gl >> 5;
                int gg = gl & 31;
                src = Bg + (size_t)(k0 + kr) * N + col0 + (gg << 2);
                dst = sb + SB_OFF + st * B_TB + kr * B_PITCH + (gg << 4);
            }
            asm volatile("cp.async.cg.shared.global [%0], [%1], 16;"
                         :: "r"(dst), "l"(src) : "memory");
        }
        asm volatile("cp.async.commit_group;" ::: "memory");
    };

    issue(0);
    issue(1);

    const int q = lane >> 2;               // 0..7
    const int s = lane & 3;                // 0..3

    for (int ch = 0; ch < NCH; ch++) {
        asm volatile("cp.async.wait_group 1;" ::: "memory");
        __syncthreads();
        if (ch + 2 < NCH) issue(ch + 2);
        else asm volatile("cp.async.commit_group;" ::: "memory");

        const int st = ch % STG;
        const uint32_t ab = sb + st * A_TB;
        const uint32_t bb = sb + SB_OFF + st * B_TB;

#pragma unroll
        for (int ks = 0; ks < 4; ks++) {
            const int k0 = ks << 3;
            uint32_t bf[4][2];
#pragma unroll
            for (int tn = 0; tn < 4; tn++) {
                const int n = wn0 + (tn << 3) + q;
                if (BNT) {
                    bf[tn][0] = lds_u(bb + sw128((n << 7) + ((k0 + s) << 2)));
                    bf[tn][1] = lds_u(bb + sw128((n << 7) + ((k0 + s + 4) << 2)));
                } else {
                    bf[tn][0] = lds_u(bb + (k0 + s) * B_PITCH + (n << 2));
                    bf[tn][1] = lds_u(bb + (k0 + s + 4) * B_PITCH + (n << 2));
                }
            }
#pragma unroll
            for (int tm = 0; tm < 4; tm++) {
                const int r = wm0 + (tm << 4) + q;
                uint32_t a0 = lds_u(ab + sw128((r << 7) + ((k0 + s) << 2)));
                uint32_t a1 = lds_u(ab + sw128(((r + 8) << 7) + ((k0 + s) << 2)));
                uint32_t a2 = lds_u(ab + sw128((r << 7) + ((k0 + s + 4) << 2)));
                uint32_t a3 = lds_u(ab + sw128(((r + 8) << 7) + ((k0 + s + 4) << 2)));
#pragma unroll
                for (int tn = 0; tn < 4; tn++)
                    mma_tf32(acc[tm][tn], a0, a1, a2, a3, bf[tn][0], bf[tn][1]);
            }
        }
        // single barrier per iteration (next iter's barrier protects reuse)
    }

    // -------- epilogue --------
    if (MODE != 3) {
#pragma unroll
        for (int tm = 0; tm < 4; tm++) {
            const size_t r_lo = (size_t)row0 + wm0 + (tm << 4) + q;
#pragma unroll
            for (int tn = 0; tn < 4; tn++) {
                const int col = col0 + wn0 + (tn << 3) + (s << 1);
                float v0 = acc[tm][tn][0], v1 = acc[tm][tn][1];
                float v2 = acc[tm][tn][2], v3 = acc[tm][tn][3];
                if (MODE == 0) {
                    const float b0 = __ldg(bias + col), b1 = __ldg(bias + col + 1);
                    v0 = rtf(v0 + b0); v1 = rtf(v1 + b1);
                    v2 = rtf(v2 + b0); v3 = rtf(v3 + b1);
                }
                *reinterpret_cast<float2*>(Cg + r_lo * N + col)       = make_float2(v0, v1);
                *reinterpret_cast<float2*>(Cg + (r_lo + 8) * N + col) = make_float2(v2, v3);
            }
        }
    } else {
        const bool diag = (row0 == col0);
        // direct tile write (scaled)
#pragma unroll
        for (int tm = 0; tm < 4; tm++) {
            const size_t r_lo = (size_t)row0 + wm0 + (tm << 4) + q;
#pragma unroll
            for (int tn = 0; tn < 4; tn++) {
                const int col = col0 + wn0 + (tn << 3) + (s << 1);
                float v0 = acc[tm][tn][0] * alpha, v1 = acc[tm][tn][1] * alpha;
                float v2 = acc[tm][tn][2] * alpha, v3 = acc[tm][tn][3] * alpha;
                acc[tm][tn][0] = v0; acc[tm][tn][1] = v1;
                acc[tm][tn][2] = v2; acc[tm][tn][3] = v3;
                *reinterpret_cast<float2*>(Cg + r_lo * N + col)       = make_float2(v0, v1);
                *reinterpret_cast<float2*>(Cg + (r_lo + 8) * N + col) = make_float2(v2, v3);
            }
        }
        if (!diag) {
            // stage transposed (smem[n][m] = acc(m,n)), then coalesced mirror write
            asm volatile("cp.async.wait_group 0;" ::: "memory");
            __syncthreads();
#pragma unroll
            for (int tm = 0; tm < 4; tm++) {
                const int m = wm0 + (tm << 4) + q;
#pragma unroll
                for (int tn = 0; tn < 4; tn++) {
                    const int n = wn0 + (tn << 3) + (s << 1);
                    sts_f(sb + (uint32_t)(n       * TPITCH + m)     * 4, acc[tm][tn][0]);
                    sts_f(sb + (uint32_t)((n + 1) * TPITCH + m)     * 4, acc[tm][tn][1]);
                    sts_f(sb + (uint32_t)(n       * TPITCH + m + 8) * 4, acc[tm][tn][2]);
                    sts_f(sb + (uint32_t)((n + 1) * TPITCH + m + 8) * 4, acc[tm][tn][3]);
                }
            }
            __syncthreads();
            // 256 threads: 128 rows(n), 2 threads/row, 64 cols(m) each
            const int nr   = tid >> 1;
            const int half = (tid & 1) << 6;
            float* dstrow = Cg + (size_t)(col0 + nr) * N + row0 + half;
            const uint32_t srow = sb + (uint32_t)(nr * TPITCH + half) * 4;
#pragma unroll
            for (int j = 0; j < 64; j += 4) {
                float4 v = lds_f4(srow + j * 4);
                *reinterpret_cast<float4*>(dstrow + j) = v;
            }
        }
    }
}

// ---------------------------------------------------------------------------
__global__ __launch_bounds__(256)
void round_k(const float4* __restrict__ in, float4* __restrict__ out, int n4)
{
    int i = blockIdx.x * 256 + threadIdx.x;
    if (i < n4) {
        float4 v = in[i];
        v.x = rtf(v.x); v.y = rtf(v.y); v.z = rtf(v.z); v.w = rtf(v.w);
        out[i] = v;
    }
}

// row softmax over 2048 cols; probs rounded to tf32 for GEMM3
__global__ __launch_bounds__(256)
void softmax_kernel(float* __restrict__ S)
{
    float* p = S + (size_t)blockIdx.x * SEQ;
    const int tid  = threadIdx.x;
    const int lane = tid & 31;
    const int wid  = tid >> 5;
    __shared__ float red[8];

    float v[8];
    float m = -1e30f;
#pragma unroll
    for (int k = 0; k < 8; k++) {
        v[k] = p[tid + k * 256];
        m = fmaxf(m, v[k]);
    }
#pragma unroll
    for (int o = 16; o > 0; o >>= 1)
        m = fmaxf(m, __shfl_xor_sync(0xffffffffu, m, o));
    if (lane == 0) red[wid] = m;
    __syncthreads();
    float bm = red[0];
#pragma unroll
    for (int i = 1; i < 8; i++) bm = fmaxf(bm, red[i]);
    __syncthreads();

    float sum = 0.f;
#pragma unroll
    for (int k = 0; k < 8; k++) {
        v[k] = __expf(v[k] - bm);
        sum += v[k];
    }
#pragma unroll
    for (int o = 16; o > 0; o >>= 1)
        sum += __shfl_xor_sync(0xffffffffu, sum, o);
    if (lane == 0) red[wid] = sum;
    __syncthreads();
    float total = 0.f;
#pragma unroll
    for (int i = 0; i < 8; i++) total += red[i];
    const float inv = 1.f / total;

#pragma unroll
    for (int k = 0; k < 8; k++)
        p[tid + k * 256] = rtf(v[k] * inv);
}

// ---------------------------------------------------------------------------
extern "C" void kernel_launch(void* const* d_in, const int* in_sizes, int n_in,
                              void* d_out, int out_size)
{
    const float* embd = (const float*)d_in[0];   // [8,2048,1024]
    const float* W    = (const float*)d_in[1];   // [1024,1024]
    const float* bias = (const float*)d_in[2];   // [1024]
    float* out = (float*)d_out;                  // [8,2048,1024]

    float *et, *wt, *c, *s;
    cudaGetSymbolAddress((void**)&et, g_et);
    cudaGetSymbolAddress((void**)&wt, g_wt);
    cudaGetSymbolAddress((void**)&c,  g_c);
    cudaGetSymbolAddress((void**)&s,  g_s);

    cudaFuncSetAttribute(tc_gemm<0>, cudaFuncAttributeMaxDynamicSharedMemorySize, DSMEM_NT);
    cudaFuncSetAttribute(tc_gemm<2>, cudaFuncAttributeMaxDynamicSharedMemorySize, DSMEM_NN);
    cudaFuncSetAttribute(tc_gemm<3>, cudaFuncAttributeMaxDynamicSharedMemorySize, DSMEM_NT);

    const float scale = 0.03125f;  // 1/sqrt(1024)

    // prepass: round inputs to tf32 (unbiased)
    {
        int n4e = BATCH * SEQ * EMBD / 4;
        round_k<<<n4e / 256, 256>>>((const float4*)embd, (float4*)et, n4e);
        int n4w = OUTD * EMBD / 4;
        round_k<<<n4w / 256, 256>>>((const float4*)W, (float4*)wt, n4w);
    }

    // 1) c = embd @ W^T + b  (NT, M=16384, N=1024, K=1024), c rounded to tf32
    {
        dim3 grid(OUTD / 128, (BATCH * SEQ) / 128, 1);
        tc_gemm<0><<<grid, 256, DSMEM_NT>>>(et, wt, bias, c,
                                            OUTD, EMBD, 1.0f, 0, 0, 0);
    }
    // 2) s = (c @ c^T) * scale per batch — symmetric: 136 triangular tiles
    {
        dim3 grid(136, 1, BATCH);
        tc_gemm<3><<<grid, 256, DSMEM_NT>>>(c, c, nullptr, s,
                                            SEQ, OUTD, scale,
                                            (size_t)SEQ * OUTD, (size_t)SEQ * OUTD,
                                            (size_t)SEQ * SEQ);
    }
    // 3) softmax rows (stores tf32-rounded probs)
    softmax_kernel<<<BATCH * SEQ, 256>>>(s);

    // 4) out = P @ c  (NN, M=2048, N=1024, K=2048)
    {
        dim3 grid(OUTD / 128, SEQ / 128, BATCH);
        tc_gemm<2><<<grid, 256, DSMEM_NN>>>(s, c, nullptr, out,
                                            OUTD, SEQ, 1.0f,
                                            (size_t)SEQ * SEQ, (size_t)SEQ * OUTD,
                                            (size_t)SEQ * OUTD);
    }
}

// round 5
// speedup vs baseline: 4.4866x; 1.8134x over previous
#include <cuda_runtime.h>
#include <cuda_bf16.h>
#include <cstdint>

#define BATCH 8
#define SEQ   2048
#define EMBD  1024
#define OUTD  1024

// Scratch (device globals; allocations are forbidden)
__device__ __align__(256) float g_et[(size_t)BATCH * SEQ * EMBD];  // tf32 embd  64MB
__device__ __align__(256) float g_wt[(size_t)OUTD * EMBD];         // tf32 W      4MB
__device__ __align__(256) float g_c [(size_t)BATCH * SEQ * OUTD];  // c (tf32)   64MB
__device__ __align__(256) float g_s [(size_t)BATCH * SEQ * SEQ];   // scores    128MB

// ---------------------------------------------------------------------------
__device__ __forceinline__ uint32_t smem_u32(const void* p) {
    uint32_t a;
    asm("{ .reg .u64 t; cvta.to.shared.u64 t, %1; cvt.u32.u64 %0, t; }"
        : "=r"(a) : "l"(p));
    return a;
}
// fp32 -> tf32 round-to-nearest (unbiased)
__device__ __forceinline__ float rtf(float x) {
    uint32_t u;
    asm("cvt.rna.tf32.f32 %0, %1;" : "=r"(u) : "f"(x));
    return __uint_as_float(u);
}
__device__ __forceinline__ uint32_t lds_u(uint32_t a) {
    uint32_t v;
    asm volatile("ld.shared.b32 %0, [%1];" : "=r"(v) : "r"(a));
    return v;
}
__device__ __forceinline__ void sts_f(uint32_t a, float v) {
    asm volatile("st.shared.b32 [%0], %1;" :: "r"(a), "f"(v) : "memory");
}
__device__ __forceinline__ float4 lds_f4(uint32_t a) {
    float4 v;
    asm volatile("ld.shared.v4.f32 {%0,%1,%2,%3}, [%4];"
                 : "=f"(v.x), "=f"(v.y), "=f"(v.z), "=f"(v.w) : "r"(a));
    return v;
}
__device__ __forceinline__ void mma_tf32(float c[4], uint32_t a0, uint32_t a1,
                                         uint32_t a2, uint32_t a3,
                                         uint32_t b0, uint32_t b1) {
    asm volatile(
        "mma.sync.aligned.m16n8k8.row.col.f32.tf32.tf32.f32 "
        "{%0,%1,%2,%3}, {%4,%5,%6,%7}, {%8,%9}, {%0,%1,%2,%3};"
        : "+f"(c[0]), "+f"(c[1]), "+f"(c[2]), "+f"(c[3])
        : "r"(a0), "r"(a1), "r"(a2), "r"(a3), "r"(b0), "r"(b1));
}
__device__ __forceinline__ uint32_t sw128(uint32_t bo) {
    return bo ^ ((bo >> 3) & 0x70);
}

// ---------------------------------------------------------------------------
// tf32 mma.sync GEMM: 128x128 CTA tile, BK=32, 4 warps (2m x 2n), warp 64x64.
// 128 threads, 2 CTAs/SM. LDS/MMA ratio 1.0 -> tensor-bound.
// MODE 0: NT, epilogue = +bias, round->tf32      (GEMM1: c = embd@W^T + b)
// MODE 2: NN, plain                              (GEMM3: out = P@c)
// MODE 3: NT, *alpha, SYMMETRIC triangular tiles (GEMM2: logits, mirrored)
// ---------------------------------------------------------------------------
#define STG     3
#define A_TB    16384                    // 128 rows x 128B
#define SB_OFF  (STG * A_TB)             // 49152
#define B_TB_NT 16384
#define B_PITCH 544                      // NN: 136 floats/row (conflict-free)
#define B_TB_NN (32 * B_PITCH)           // 17408
#define DSMEM_NT (SB_OFF + STG * B_TB_NT + 1024)
#define DSMEM_NN (SB_OFF + STG * B_TB_NN + 1024)
#define TPITCH  132                      // transpose staging pitch (floats)

template <int MODE>
__global__ __launch_bounds__(128, 2)
void tc_gemm(const float* __restrict__ Ag, const float* __restrict__ Bg,
             const float* __restrict__ bias, float* __restrict__ Cg,
             int N, int K, float alpha,
             size_t strA, size_t strB, size_t strC)
{
    constexpr bool BNT = (MODE != 2);
    constexpr int  B_TB = BNT ? B_TB_NT : B_TB_NN;

    extern __shared__ char dsm[];
    const uint32_t sb = (smem_u32(dsm) + 1023u) & ~1023u;

    Ag += (size_t)blockIdx.z * strA;
    Bg += (size_t)blockIdx.z * strB;
    Cg += (size_t)blockIdx.z * strC;

    const int tid  = threadIdx.x;
    const int lane = tid & 31;
    const int wid  = tid >> 5;           // 0..3
    const int wm0  = (wid & 1) * 64;     // warp m offset
    const int wn0  = (wid >> 1) * 64;    // warp n offset

    int row0, col0;
    if (MODE == 3) {
        const int t = blockIdx.x;
        int r = (int)((sqrtf(8.0f * (float)t + 1.0f) - 1.0f) * 0.5f);
        while ((r + 1) * (r + 2) / 2 <= t) r++;
        while (r * (r + 1) / 2 > t)        r--;
        const int cc = t - r * (r + 1) / 2;
        row0 = r  * 128;
        col0 = cc * 128;
    } else {
        row0 = blockIdx.y * 128;
        col0 = blockIdx.x * 128;
    }

    const int NCH = K >> 5;

    float acc[4][8][4];
#pragma unroll
    for (int i = 0; i < 4; i++)
#pragma unroll
        for (int j = 0; j < 8; j++)
#pragma unroll
            for (int r = 0; r < 4; r++) acc[i][j][r] = 0.f;

    auto issue = [&](int ch) {
        const int st = ch % STG;
        const int k0 = ch << 5;
#pragma unroll
        for (int i = 0; i < 16; i++) {
            int g   = tid + (i << 7);          // 0..2047
            int isB = g >> 10;
            int gl  = g & 1023;
            const float* src;
            uint32_t dst;
            if (!isB) {                        // A: 128 rows x 8 granules
                int r  = gl >> 3;
                int gg = gl & 7;
                src = Ag + (size_t)(row0 + r) * K + k0 + (gg << 2);
                dst = sb + st * A_TB + sw128((r << 7) + (gg << 4));
            } else if (BNT) {                  // B NT: [n][k], 128 rows x 8 gran
                int r  = gl >> 3;
                int gg = gl & 7;
                src = Bg + (size_t)(col0 + r) * K + k0 + (gg << 2);
                dst = sb + SB_OFF + st * B_TB + sw128((r << 7) + (gg << 4));
            } else {                           // B NN: [k][n], 32 rows x 32 gran
                int kr = gl >> 5;
                int gg = gl & 31;
                src = Bg + (size_t)(k0 + kr) * N + col0 + (gg << 2);
                dst = sb + SB_OFF + st * B_TB + kr * B_PITCH + (gg << 4);
            }
            asm volatile("cp.async.cg.shared.global [%0], [%1], 16;"
                         :: "r"(dst), "l"(src) : "memory");
        }
        asm volatile("cp.async.commit_group;" ::: "memory");
    };

    issue(0);
    issue(1);

    const int q = lane >> 2;               // 0..7
    const int s = lane & 3;                // 0..3

    for (int ch = 0; ch < NCH; ch++) {
        asm volatile("cp.async.wait_group 1;" ::: "memory");
        __syncthreads();
        if (ch + 2 < NCH) issue(ch + 2);
        else asm volatile("cp.async.commit_group;" ::: "memory");

        const int st = ch % STG;
        const uint32_t ab = sb + st * A_TB;
        const uint32_t bb = sb + SB_OFF + st * B_TB;

#pragma unroll
        for (int ks = 0; ks < 4; ks++) {
            const int k0 = ks << 3;
            uint32_t bf[8][2];
#pragma unroll
            for (int tn = 0; tn < 8; tn++) {
                const int n = wn0 + (tn << 3) + q;
                if (BNT) {
                    bf[tn][0] = lds_u(bb + sw128((n << 7) + ((k0 + s) << 2)));
                    bf[tn][1] = lds_u(bb + sw128((n << 7) + ((k0 + s + 4) << 2)));
                } else {
                    bf[tn][0] = lds_u(bb + (k0 + s) * B_PITCH + (n << 2));
                    bf[tn][1] = lds_u(bb + (k0 + s + 4) * B_PITCH + (n << 2));
                }
            }
#pragma unroll
            for (int tm = 0; tm < 4; tm++) {
                const int r = wm0 + (tm << 4) + q;
                uint32_t a0 = lds_u(ab + sw128((r << 7) + ((k0 + s) << 2)));
                uint32_t a1 = lds_u(ab + sw128(((r + 8) << 7) + ((k0 + s) << 2)));
                uint32_t a2 = lds_u(ab + sw128((r << 7) + ((k0 + s + 4) << 2)));
                uint32_t a3 = lds_u(ab + sw128(((r + 8) << 7) + ((k0 + s + 4) << 2)));
#pragma unroll
                for (int tn = 0; tn < 8; tn++)
                    mma_tf32(acc[tm][tn], a0, a1, a2, a3, bf[tn][0], bf[tn][1]);
            }
        }
        // single barrier per iteration (next iter's barrier protects reuse)
    }

    // -------- epilogue --------
    if (MODE != 3) {
#pragma unroll
        for (int tm = 0; tm < 4; tm++) {
            const size_t r_lo = (size_t)row0 + wm0 + (tm << 4) + q;
#pragma unroll
            for (int tn = 0; tn < 8; tn++) {
                const int col = col0 + wn0 + (tn << 3) + (s << 1);
                float v0 = acc[tm][tn][0], v1 = acc[tm][tn][1];
                float v2 = acc[tm][tn][2], v3 = acc[tm][tn][3];
                if (MODE == 0) {
                    const float b0 = __ldg(bias + col), b1 = __ldg(bias + col + 1);
                    v0 = rtf(v0 + b0); v1 = rtf(v1 + b1);
                    v2 = rtf(v2 + b0); v3 = rtf(v3 + b1);
                }
                *reinterpret_cast<float2*>(Cg + r_lo * N + col)       = make_float2(v0, v1);
                *reinterpret_cast<float2*>(Cg + (r_lo + 8) * N + col) = make_float2(v2, v3);
            }
        }
    } else {
        const bool diag = (row0 == col0);
#pragma unroll
        for (int tm = 0; tm < 4; tm++) {
            const size_t r_lo = (size_t)row0 + wm0 + (tm << 4) + q;
#pragma unroll
            for (int tn = 0; tn < 8; tn++) {
                const int col = col0 + wn0 + (tn << 3) + (s << 1);
                float v0 = acc[tm][tn][0] * alpha, v1 = acc[tm][tn][1] * alpha;
                float v2 = acc[tm][tn][2] * alpha, v3 = acc[tm][tn][3] * alpha;
                acc[tm][tn][0] = v0; acc[tm][tn][1] = v1;
                acc[tm][tn][2] = v2; acc[tm][tn][3] = v3;
                *reinterpret_cast<float2*>(Cg + r_lo * N + col)       = make_float2(v0, v1);
                *reinterpret_cast<float2*>(Cg + (r_lo + 8) * N + col) = make_float2(v2, v3);
            }
        }
        if (!diag) {
            // stage transposed (smem[n][m] = acc(m,n)), then coalesced mirror write
            asm volatile("cp.async.wait_group 0;" ::: "memory");
            __syncthreads();
#pragma unroll
            for (int tm = 0; tm < 4; tm++) {
                const int m = wm0 + (tm << 4) + q;
#pragma unroll
                for (int tn = 0; tn < 8; tn++) {
                    const int n = wn0 + (tn << 3) + (s << 1);
                    sts_f(sb + (uint32_t)(n       * TPITCH + m)     * 4, acc[tm][tn][0]);
                    sts_f(sb + (uint32_t)((n + 1) * TPITCH + m)     * 4, acc[tm][tn][1]);
                    sts_f(sb + (uint32_t)(n       * TPITCH + m + 8) * 4, acc[tm][tn][2]);
                    sts_f(sb + (uint32_t)((n + 1) * TPITCH + m + 8) * 4, acc[tm][tn][3]);
                }
            }
            __syncthreads();
            // 128 threads: one n-row each, 128 cols
            float* dstrow = Cg + (size_t)(col0 + tid) * N + row0;
            const uint32_t srow = sb + (uint32_t)(tid * TPITCH) * 4;
#pragma unroll
            for (int j = 0; j < 128; j += 4) {
                float4 v = lds_f4(srow + j * 4);
                *reinterpret_cast<float4*>(dstrow + j) = v;
            }
        }
    }
}

// ---------------------------------------------------------------------------
__global__ __launch_bounds__(256)
void round_k(const float4* __restrict__ in, float4* __restrict__ out, int n4)
{
    int i = blockIdx.x * 256 + threadIdx.x;
    if (i < n4) {
        float4 v = in[i];
        v.x = rtf(v.x); v.y = rtf(v.y); v.z = rtf(v.z); v.w = rtf(v.w);
        out[i] = v;
    }
}

// row softmax over 2048 cols (float4 vectorized); probs rounded to tf32
__global__ __launch_bounds__(256)
void softmax_kernel(float* __restrict__ S)
{
    float4* p4 = reinterpret_cast<float4*>(S + (size_t)blockIdx.x * SEQ);
    const int tid  = threadIdx.x;
    const int lane = tid & 31;
    const int wid  = tid >> 5;
    __shared__ float red[8];

    float4 u0 = p4[tid], u1 = p4[tid + 256];
    float m = fmaxf(fmaxf(fmaxf(u0.x, u0.y), fmaxf(u0.z, u0.w)),
                    fmaxf(fmaxf(u1.x, u1.y), fmaxf(u1.z, u1.w)));
#pragma unroll
    for (int o = 16; o > 0; o >>= 1)
        m = fmaxf(m, __shfl_xor_sync(0xffffffffu, m, o));
    if (lane == 0) red[wid] = m;
    __syncthreads();
    float bm = red[0];
#pragma unroll
    for (int i = 1; i < 8; i++) bm = fmaxf(bm, red[i]);
    __syncthreads();

    u0.x = __expf(u0.x - bm); u0.y = __expf(u0.y - bm);
    u0.z = __expf(u0.z - bm); u0.w = __expf(u0.w - bm);
    u1.x = __expf(u1.x - bm); u1.y = __expf(u1.y - bm);
    u1.z = __expf(u1.z - bm); u1.w = __expf(u1.w - bm);
    float sum = (u0.x + u0.y) + (u0.z + u0.w) + (u1.x + u1.y) + (u1.z + u1.w);
#pragma unroll
    for (int o = 16; o > 0; o >>= 1)
        sum += __shfl_xor_sync(0xffffffffu, sum, o);
    if (lane == 0) red[wid] = sum;
    __syncthreads();
    float total = 0.f;
#pragma unroll
    for (int i = 0; i < 8; i++) total += red[i];
    const float inv = 1.f / total;

    u0.x = rtf(u0.x * inv); u0.y = rtf(u0.y * inv);
    u0.z = rtf(u0.z * inv); u0.w = rtf(u0.w * inv);
    u1.x = rtf(u1.x * inv); u1.y = rtf(u1.y * inv);
    u1.z = rtf(u1.z * inv); u1.w = rtf(u1.w * inv);
    p4[tid]       = u0;
    p4[tid + 256] = u1;
}

// ---------------------------------------------------------------------------
extern "C" void kernel_launch(void* const* d_in, const int* in_sizes, int n_in,
                              void* d_out, int out_size)
{
    const float* embd = (const float*)d_in[0];   // [8,2048,1024]
    const float* W    = (const float*)d_in[1];   // [1024,1024]
    const float* bias = (const float*)d_in[2];   // [1024]
    float* out = (float*)d_out;                  // [8,2048,1024]

    float *et, *wt, *c, *s;
    cudaGetSymbolAddress((void**)&et, g_et);
    cudaGetSymbolAddress((void**)&wt, g_wt);
    cudaGetSymbolAddress((void**)&c,  g_c);
    cudaGetSymbolAddress((void**)&s,  g_s);

    cudaFuncSetAttribute(tc_gemm<0>, cudaFuncAttributeMaxDynamicSharedMemorySize, DSMEM_NT);
    cudaFuncSetAttribute(tc_gemm<2>, cudaFuncAttributeMaxDynamicSharedMemorySize, DSMEM_NN);
    cudaFuncSetAttribute(tc_gemm<3>, cudaFuncAttributeMaxDynamicSharedMemorySize, DSMEM_NT);

    const float scale = 0.03125f;  // 1/sqrt(1024)

    // prepass: round inputs to tf32 (unbiased)
    {
        int n4e = BATCH * SEQ * EMBD / 4;
        round_k<<<n4e / 256, 256>>>((const float4*)embd, (float4*)et, n4e);
        int n4w = OUTD * EMBD / 4;
        round_k<<<n4w / 256, 256>>>((const float4*)W, (float4*)wt, n4w);
    }

    // 1) c = embd @ W^T + b  (NT, M=16384, N=1024, K=1024), c rounded to tf32
    {
        dim3 grid(OUTD / 128, (BATCH * SEQ) / 128, 1);
        tc_gemm<0><<<grid, 128, DSMEM_NT>>>(et, wt, bias, c,
                                            OUTD, EMBD, 1.0f, 0, 0, 0);
    }
    // 2) s = (c @ c^T) * scale per batch — symmetric: 136 triangular tiles
    {
        dim3 grid(136, 1, BATCH);
        tc_gemm<3><<<grid, 128, DSMEM_NT>>>(c, c, nullptr, s,
                                            SEQ, OUTD, scale,
                                            (size_t)SEQ * OUTD, (size_t)SEQ * OUTD,
                                            (size_t)SEQ * SEQ);
    }
    // 3) softmax rows (stores tf32-rounded probs)
    softmax_kernel<<<BATCH * SEQ, 256>>>(s);

    // 4) out = P @ c  (NN, M=2048, N=1024, K=2048)
    {
        dim3 grid(OUTD / 128, SEQ / 128, BATCH);
        tc_gemm<2><<<grid, 128, DSMEM_NN>>>(s, c, nullptr, out,
                                            OUTD, SEQ, 1.0f,
                                            (size_t)SEQ * SEQ, (size_t)SEQ * OUTD,
                                            (size_t)SEQ * OUTD);
    }
}

// round 6
// speedup vs baseline: 4.5462x; 1.0133x over previous
#include <cuda_runtime.h>
#include <cuda_bf16.h>
#include <cstdint>

#define BATCH 8
#define SEQ   2048
#define EMBD  1024
#define OUTD  1024

// Scratch (device globals; allocations are forbidden)
__device__ __align__(256) float g_et[(size_t)BATCH * SEQ * EMBD];  // tf32 embd  64MB
__device__ __align__(256) float g_wt[(size_t)OUTD * EMBD];         // tf32 W      4MB
__device__ __align__(256) float g_c [(size_t)BATCH * SEQ * OUTD];  // c (tf32)   64MB
__device__ __align__(256) float g_s [(size_t)BATCH * SEQ * SEQ];   // scores    128MB

// ---------------------------------------------------------------------------
__device__ __forceinline__ uint32_t smem_u32(const void* p) {
    uint32_t a;
    asm("{ .reg .u64 t; cvta.to.shared.u64 t, %1; cvt.u32.u64 %0, t; }"
        : "=r"(a) : "l"(p));
    return a;
}
// fp32 -> tf32 round-to-nearest (unbiased)
__device__ __forceinline__ float rtf(float x) {
    uint32_t u;
    asm("cvt.rna.tf32.f32 %0, %1;" : "=r"(u) : "f"(x));
    return __uint_as_float(u);
}
__device__ __forceinline__ uint32_t lds_u(uint32_t a) {
    uint32_t v;
    asm volatile("ld.shared.b32 %0, [%1];" : "=r"(v) : "r"(a));
    return v;
}
__device__ __forceinline__ void sts_f(uint32_t a, float v) {
    asm volatile("st.shared.b32 [%0], %1;" :: "r"(a), "f"(v) : "memory");
}
__device__ __forceinline__ float4 lds_f4(uint32_t a) {
    float4 v;
    asm volatile("ld.shared.v4.f32 {%0,%1,%2,%3}, [%4];"
                 : "=f"(v.x), "=f"(v.y), "=f"(v.z), "=f"(v.w) : "r"(a));
    return v;
}
__device__ __forceinline__ void mma_tf32(float c[4], uint32_t a0, uint32_t a1,
                                         uint32_t a2, uint32_t a3,
                                         uint32_t b0, uint32_t b1) {
    asm volatile(
        "mma.sync.aligned.m16n8k8.row.col.f32.tf32.tf32.f32 "
        "{%0,%1,%2,%3}, {%4,%5,%6,%7}, {%8,%9}, {%0,%1,%2,%3};"
        : "+f"(c[0]), "+f"(c[1]), "+f"(c[2]), "+f"(c[3])
        : "r"(a0), "r"(a1), "r"(a2), "r"(a3), "r"(b0), "r"(b1));
}
__device__ __forceinline__ uint32_t sw128(uint32_t bo) {
    return bo ^ ((bo >> 3) & 0x70);
}

// ---------------------------------------------------------------------------
// tf32 mma.sync GEMM: 128x128 CTA tile, BK=32, 4 warps (2m x 2n), warp 64x64.
// 128 threads, 2 CTAs/SM. Stage index compile-time via 3x-unrolled mainloop.
// MODE 0: NT, epilogue = +bias, round->tf32      (GEMM1: c = embd@W^T + b)
// MODE 2: NN, plain                              (GEMM3: out = P@c)
// MODE 3: NT, *alpha, SYMMETRIC triangular tiles (GEMM2: logits, mirrored)
// ---------------------------------------------------------------------------
#define STG     3
#define A_TB    16384                    // 128 rows x 128B
#define SB_OFF  (STG * A_TB)             // 49152
#define B_TB_NT 16384
#define B_PITCH 544                      // NN: 136 floats/row (conflict-free)
#define B_TB_NN (32 * B_PITCH)           // 17408
#define DSMEM_NT (SB_OFF + STG * B_TB_NT + 1024)
#define DSMEM_NN (SB_OFF + STG * B_TB_NN + 1024)
#define TPITCH  132                      // transpose staging pitch (floats)

template <int MODE>
__global__ __launch_bounds__(128, 2)
void tc_gemm(const float* __restrict__ Ag, const float* __restrict__ Bg,
             const float* __restrict__ bias, float* __restrict__ Cg,
             int N, int K, float alpha,
             size_t strA, size_t strB, size_t strC)
{
    constexpr bool BNT = (MODE != 2);
    constexpr int  B_TB = BNT ? B_TB_NT : B_TB_NN;

    extern __shared__ char dsm[];
    const uint32_t sb = (smem_u32(dsm) + 1023u) & ~1023u;

    Ag += (size_t)blockIdx.z * strA;
    Bg += (size_t)blockIdx.z * strB;
    Cg += (size_t)blockIdx.z * strC;

    const int tid  = threadIdx.x;
    const int lane = tid & 31;
    const int wid  = tid >> 5;           // 0..3
    const int wm0  = (wid & 1) * 64;     // warp m offset
    const int wn0  = (wid >> 1) * 64;    // warp n offset

    int row0, col0;
    if (MODE == 3) {
        const int t = blockIdx.x;
        int r = (int)((sqrtf(8.0f * (float)t + 1.0f) - 1.0f) * 0.5f);
        while ((r + 1) * (r + 2) / 2 <= t) r++;
        while (r * (r + 1) / 2 > t)        r--;
        const int cc = t - r * (r + 1) / 2;
        row0 = r  * 128;
        col0 = cc * 128;
    } else {
        row0 = blockIdx.y * 128;
        col0 = blockIdx.x * 128;
    }

    const int NCH = K >> 5;
    const int q = lane >> 2;             // 0..7
    const int s = lane & 3;              // 0..3

    float acc[4][8][4];
#pragma unroll
    for (int i = 0; i < 4; i++)
#pragma unroll
        for (int j = 0; j < 8; j++)
#pragma unroll
            for (int r = 0; r < 4; r++) acc[i][j][r] = 0.f;

    auto issue = [&](int ch, int st) {
        const int k0 = ch << 5;
#pragma unroll
        for (int i = 0; i < 16; i++) {
            int g   = tid + (i << 7);          // 0..2047
            int isB = g >> 10;
            int gl  = g & 1023;
            const float* src;
            uint32_t dst;
            if (!isB) {                        // A: 128 rows x 8 granules
                int r  = gl >> 3;
                int gg = gl & 7;
                src = Ag + (size_t)(row0 + r) * K + k0 + (gg << 2);
                dst = sb + st * A_TB + sw128((r << 7) + (gg << 4));
            } else if (BNT) {                  // B NT: [n][k], 128 rows x 8 gran
                int r  = gl >> 3;
                int gg = gl & 7;
                src = Bg + (size_t)(col0 + r) * K + k0 + (gg << 2);
                dst = sb + SB_OFF + st * B_TB + sw128((r << 7) + (gg << 4));
            } else {                           // B NN: [k][n], 32 rows x 32 gran
                int kr = gl >> 5;
                int gg = gl & 31;
                src = Bg + (size_t)(k0 + kr) * N + col0 + (gg << 2);
                dst = sb + SB_OFF + st * B_TB + kr * B_PITCH + (gg << 4);
            }
            asm volatile("cp.async.cg.shared.global [%0], [%1], 16;"
                         :: "r"(dst), "l"(src) : "memory");
        }
        asm volatile("cp.async.commit_group;" ::: "memory");
    };

    // one chunk: wait, barrier, prefetch ch+2 into stage (st+2)%3, compute st
    auto step = [&](int ch, const int st) {
        asm volatile("cp.async.wait_group 1;" ::: "memory");
        __syncthreads();
        if (ch + 2 < NCH) issue(ch + 2, (st + 2) % STG);
        else asm volatile("cp.async.commit_group;" ::: "memory");

        const uint32_t ab = sb + st * A_TB;
        const uint32_t bb = sb + SB_OFF + st * B_TB;

#pragma unroll
        for (int ks = 0; ks < 4; ks++) {
            const int k0 = ks << 3;
            uint32_t bf[16], af[16];
#pragma unroll
            for (int tn = 0; tn < 8; tn++) {
                const int n = wn0 + (tn << 3) + q;
                if (BNT) {
                    bf[tn * 2]     = lds_u(bb + sw128((n << 7) + ((k0 + s) << 2)));
                    bf[tn * 2 + 1] = lds_u(bb + sw128((n << 7) + ((k0 + s + 4) << 2)));
                } else {
                    bf[tn * 2]     = lds_u(bb + (k0 + s) * B_PITCH + (n << 2));
                    bf[tn * 2 + 1] = lds_u(bb + (k0 + s + 4) * B_PITCH + (n << 2));
                }
            }
#pragma unroll
            for (int tm = 0; tm < 4; tm++) {
                const int r = wm0 + (tm << 4) + q;
                af[tm * 4 + 0] = lds_u(ab + sw128((r << 7) + ((k0 + s) << 2)));
                af[tm * 4 + 1] = lds_u(ab + sw128(((r + 8) << 7) + ((k0 + s) << 2)));
                af[tm * 4 + 2] = lds_u(ab + sw128((r << 7) + ((k0 + s + 4) << 2)));
                af[tm * 4 + 3] = lds_u(ab + sw128(((r + 8) << 7) + ((k0 + s + 4) << 2)));
            }
#pragma unroll
            for (int tm = 0; tm < 4; tm++)
#pragma unroll
                for (int tn = 0; tn < 8; tn++)
                    mma_tf32(acc[tm][tn], af[tm * 4], af[tm * 4 + 1],
                             af[tm * 4 + 2], af[tm * 4 + 3],
                             bf[tn * 2], bf[tn * 2 + 1]);
        }
    };

    issue(0, 0);
    issue(1, 1);

    int ch = 0;
#pragma unroll 1
    for (; ch + 3 <= NCH; ch += 3) {
        step(ch,     0);
        step(ch + 1, 1);
        step(ch + 2, 2);
    }
    if (ch < NCH) { step(ch, 0); ch++; }
    if (ch < NCH) { step(ch, 1); }

    // -------- epilogue --------
    if (MODE != 3) {
#pragma unroll
        for (int tm = 0; tm < 4; tm++) {
            const size_t r_lo = (size_t)row0 + wm0 + (tm << 4) + q;
#pragma unroll
            for (int tn = 0; tn < 8; tn++) {
                const int col = col0 + wn0 + (tn << 3) + (s << 1);
                float v0 = acc[tm][tn][0], v1 = acc[tm][tn][1];
                float v2 = acc[tm][tn][2], v3 = acc[tm][tn][3];
                if (MODE == 0) {
                    const float b0 = __ldg(bias + col), b1 = __ldg(bias + col + 1);
                    v0 = rtf(v0 + b0); v1 = rtf(v1 + b1);
                    v2 = rtf(v2 + b0); v3 = rtf(v3 + b1);
                }
                *reinterpret_cast<float2*>(Cg + r_lo * N + col)       = make_float2(v0, v1);
                *reinterpret_cast<float2*>(Cg + (r_lo + 8) * N + col) = make_float2(v2, v3);
            }
        }
    } else {
        const bool diag = (row0 == col0);
#pragma unroll
        for (int tm = 0; tm < 4; tm++) {
            const size_t r_lo = (size_t)row0 + wm0 + (tm << 4) + q;
#pragma unroll
            for (int tn = 0; tn < 8; tn++) {
                const int col = col0 + wn0 + (tn << 3) + (s << 1);
                float v0 = acc[tm][tn][0] * alpha, v1 = acc[tm][tn][1] * alpha;
                float v2 = acc[tm][tn][2] * alpha, v3 = acc[tm][tn][3] * alpha;
                acc[tm][tn][0] = v0; acc[tm][tn][1] = v1;
                acc[tm][tn][2] = v2; acc[tm][tn][3] = v3;
                *reinterpret_cast<float2*>(Cg + r_lo * N + col)       = make_float2(v0, v1);
                *reinterpret_cast<float2*>(Cg + (r_lo + 8) * N + col) = make_float2(v2, v3);
            }
        }
        if (!diag) {
            // stage transposed (smem[n][m] = acc(m,n)), then coalesced mirror write
            asm volatile("cp.async.wait_group 0;" ::: "memory");
            __syncthreads();
#pragma unroll
            for (int tm = 0; tm < 4; tm++) {
                const int m = wm0 + (tm << 4) + q;
#pragma unroll
                for (int tn = 0; tn < 8; tn++) {
                    const int n = wn0 + (tn << 3) + (s << 1);
                    sts_f(sb + (uint32_t)(n       * TPITCH + m)     * 4, acc[tm][tn][0]);
                    sts_f(sb + (uint32_t)((n + 1) * TPITCH + m)     * 4, acc[tm][tn][1]);
                    sts_f(sb + (uint32_t)(n       * TPITCH + m + 8) * 4, acc[tm][tn][2]);
                    sts_f(sb + (uint32_t)((n + 1) * TPITCH + m + 8) * 4, acc[tm][tn][3]);
                }
            }
            __syncthreads();
            // 128 threads: one n-row each, 128 cols
            float* dstrow = Cg + (size_t)(col0 + tid) * N + row0;
            const uint32_t srow = sb + (uint32_t)(tid * TPITCH) * 4;
#pragma unroll
            for (int j = 0; j < 128; j += 4) {
                float4 v = lds_f4(srow + j * 4);
                *reinterpret_cast<float4*>(dstrow + j) = v;
            }
        }
    }
}

// ---------------------------------------------------------------------------
__global__ __launch_bounds__(256)
void round_k(const float4* __restrict__ in, float4* __restrict__ out, int n4)
{
    int i = blockIdx.x * 256 + threadIdx.x;
    if (i < n4) {
        float4 v = in[i];
        v.x = rtf(v.x); v.y = rtf(v.y); v.z = rtf(v.z); v.w = rtf(v.w);
        out[i] = v;
    }
}

// row softmax over 2048 cols (float4 vectorized); probs rounded to tf32
__global__ __launch_bounds__(256)
void softmax_kernel(float* __restrict__ S)
{
    float4* p4 = reinterpret_cast<float4*>(S + (size_t)blockIdx.x * SEQ);
    const int tid  = threadIdx.x;
    const int lane = tid & 31;
    const int wid  = tid >> 5;
    __shared__ float red[8];

    float4 u0 = p4[tid], u1 = p4[tid + 256];
    float m = fmaxf(fmaxf(fmaxf(u0.x, u0.y), fmaxf(u0.z, u0.w)),
                    fmaxf(fmaxf(u1.x, u1.y), fmaxf(u1.z, u1.w)));
#pragma unroll
    for (int o = 16; o > 0; o >>= 1)
        m = fmaxf(m, __shfl_xor_sync(0xffffffffu, m, o));
    if (lane == 0) red[wid] = m;
    __syncthreads();
    float bm = red[0];
#pragma unroll
    for (int i = 1; i < 8; i++) bm = fmaxf(bm, red[i]);
    __syncthreads();

    u0.x = __expf(u0.x - bm); u0.y = __expf(u0.y - bm);
    u0.z = __expf(u0.z - bm); u0.w = __expf(u0.w - bm);
    u1.x = __expf(u1.x - bm); u1.y = __expf(u1.y - bm);
    u1.z = __expf(u1.z - bm); u1.w = __expf(u1.w - bm);
    float sum = (u0.x + u0.y) + (u0.z + u0.w) + (u1.x + u1.y) + (u1.z + u1.w);
#pragma unroll
    for (int o = 16; o > 0; o >>= 1)
        sum += __shfl_xor_sync(0xffffffffu, sum, o);
    if (lane == 0) red[wid] = sum;
    __syncthreads();
    float total = 0.f;
#pragma unroll
    for (int i = 0; i < 8; i++) total += red[i];
    const float inv = 1.f / total;

    u0.x = rtf(u0.x * inv); u0.y = rtf(u0.y * inv);
    u0.z = rtf(u0.z * inv); u0.w = rtf(u0.w * inv);
    u1.x = rtf(u1.x * inv); u1.y = rtf(u1.y * inv);
    u1.z = rtf(u1.z * inv); u1.w = rtf(u1.w * inv);
    p4[tid]       = u0;
    p4[tid + 256] = u1;
}

// ---------------------------------------------------------------------------
extern "C" void kernel_launch(void* const* d_in, const int* in_sizes, int n_in,
                              void* d_out, int out_size)
{
    const float* embd = (const float*)d_in[0];   // [8,2048,1024]
    const float* W    = (const float*)d_in[1];   // [1024,1024]
    const float* bias = (const float*)d_in[2];   // [1024]
    float* out = (float*)d_out;                  // [8,2048,1024]

    float *et, *wt, *c, *s;
    cudaGetSymbolAddress((void**)&et, g_et);
    cudaGetSymbolAddress((void**)&wt, g_wt);
    cudaGetSymbolAddress((void**)&c,  g_c);
    cudaGetSymbolAddress((void**)&s,  g_s);

    cudaFuncSetAttribute(tc_gemm<0>, cudaFuncAttributeMaxDynamicSharedMemorySize, DSMEM_NT);
    cudaFuncSetAttribute(tc_gemm<2>, cudaFuncAttributeMaxDynamicSharedMemorySize, DSMEM_NN);
    cudaFuncSetAttribute(tc_gemm<3>, cudaFuncAttributeMaxDynamicSharedMemorySize, DSMEM_NT);

    const float scale = 0.03125f;  // 1/sqrt(1024)

    // prepass: round inputs to tf32 (unbiased)
    {
        int n4e = BATCH * SEQ * EMBD / 4;
        round_k<<<n4e / 256, 256>>>((const float4*)embd, (float4*)et, n4e);
        int n4w = OUTD * EMBD / 4;
        round_k<<<n4w / 256, 256>>>((const float4*)W, (float4*)wt, n4w);
    }

    // 1) c = embd @ W^T + b  (NT, M=16384, N=1024, K=1024), c rounded to tf32
    {
        dim3 grid(OUTD / 128, (BATCH * SEQ) / 128, 1);
        tc_gemm<0><<<grid, 128, DSMEM_NT>>>(et, wt, bias, c,
                                            OUTD, EMBD, 1.0f, 0, 0, 0);
    }
    // 2) s = (c @ c^T) * scale per batch — symmetric: 136 triangular tiles
    {
        dim3 grid(136, 1, BATCH);
        tc_gemm<3><<<grid, 128, DSMEM_NT>>>(c, c, nullptr, s,
                                            SEQ, OUTD, scale,
                                            (size_t)SEQ * OUTD, (size_t)SEQ * OUTD,
                                            (size_t)SEQ * SEQ);
    }
    // 3) softmax rows (stores tf32-rounded probs)
    softmax_kernel<<<BATCH * SEQ, 256>>>(s);

    // 4) out = P @ c  (NN, M=2048, N=1024, K=2048)
    {
        dim3 grid(OUTD / 128, SEQ / 128, BATCH);
        tc_gemm<2><<<grid, 128, DSMEM_NN>>>(s, c, nullptr, out,
                                            OUTD, SEQ, 1.0f,
                                            (size_t)SEQ * SEQ, (size_t)SEQ * OUTD,
                                            (size_t)SEQ * OUTD);
    }
}

// round 7
// speedup vs baseline: 4.8292x; 1.0623x over previous
#include <cuda_runtime.h>
#include <cuda_bf16.h>
#include <cstdint>

#define BATCH 8
#define SEQ   2048
#define EMBD  1024
#define OUTD  1024

// Scratch (device globals; allocations are forbidden)
__device__ __align__(256) float g_et[(size_t)BATCH * SEQ * EMBD];  // tf32 embd  64MB
__device__ __align__(256) float g_wt[(size_t)OUTD * EMBD];         // tf32 W      4MB
__device__ __align__(256) float g_c [(size_t)BATCH * SEQ * OUTD];  // c (tf32)   64MB
__device__ __align__(256) float g_ct[(size_t)BATCH * OUTD * SEQ];  // c^T (tf32) 64MB
__device__ __align__(256) float g_s [(size_t)BATCH * SEQ * SEQ];   // scores    128MB

// ---------------------------------------------------------------------------
__device__ __forceinline__ uint32_t smem_u32(const void* p) {
    uint32_t a;
    asm("{ .reg .u64 t; cvta.to.shared.u64 t, %1; cvt.u32.u64 %0, t; }"
        : "=r"(a) : "l"(p));
    return a;
}
// fp32 -> tf32 round-to-nearest (unbiased)
__device__ __forceinline__ float rtf(float x) {
    uint32_t u;
    asm("cvt.rna.tf32.f32 %0, %1;" : "=r"(u) : "f"(x));
    return __uint_as_float(u);
}
__device__ __forceinline__ void sts_f(uint32_t a, float v) {
    asm volatile("st.shared.b32 [%0], %1;" :: "r"(a), "f"(v) : "memory");
}
__device__ __forceinline__ float4 lds_f4(uint32_t a) {
    float4 v;
    asm volatile("ld.shared.v4.f32 {%0,%1,%2,%3}, [%4];"
                 : "=f"(v.x), "=f"(v.y), "=f"(v.z), "=f"(v.w) : "r"(a));
    return v;
}
// ldmatrix x4: four 8-row x 16B tiles; per-thread row address
__device__ __forceinline__ void ldsm4(uint32_t addr, uint32_t& r0, uint32_t& r1,
                                      uint32_t& r2, uint32_t& r3) {
    asm volatile("ldmatrix.sync.aligned.m8n8.x4.shared.b16 {%0,%1,%2,%3}, [%4];"
                 : "=r"(r0), "=r"(r1), "=r"(r2), "=r"(r3) : "r"(addr));
}
__device__ __forceinline__ void mma_tf32(float c[4], uint32_t a0, uint32_t a1,
                                         uint32_t a2, uint32_t a3,
                                         uint32_t b0, uint32_t b1) {
    asm volatile(
        "mma.sync.aligned.m16n8k8.row.col.f32.tf32.tf32.f32 "
        "{%0,%1,%2,%3}, {%4,%5,%6,%7}, {%8,%9}, {%0,%1,%2,%3};"
        : "+f"(c[0]), "+f"(c[1]), "+f"(c[2]), "+f"(c[3])
        : "r"(a0), "r"(a1), "r"(a2), "r"(a3), "r"(b0), "r"(b1));
}
__device__ __forceinline__ uint32_t sw128(uint32_t bo) {
    return bo ^ ((bo >> 3) & 0x70);
}

// ---------------------------------------------------------------------------
// tf32 mma.sync GEMM (all NT): 128x128 CTA tile, BK=32, 4 warps, warp 64x64.
// ldmatrix.x4 fragment loads (8 LDSM per k-step replace 32 LDS).
// MODE 0: epilogue = +bias, round->tf32, write C AND C^T  (GEMM1)
// MODE 1: plain                                            (GEMM3)
// MODE 3: *alpha, SYMMETRIC triangular tiles, mirrored     (GEMM2)
// ---------------------------------------------------------------------------
#define STG     3
#define A_TB    16384                    // 128 rows x 128B
#define SB_OFF  (STG * A_TB)             // 49152
#define B_TB    16384
#define DSMEM   (SB_OFF + STG * B_TB + 1024)
#define TPITCH  132                      // transpose staging pitch (floats)

template <int MODE>
__global__ __launch_bounds__(128, 2)
void tc_gemm(const float* __restrict__ Ag, const float* __restrict__ Bg,
             const float* __restrict__ bias, float* __restrict__ Cg,
             float* __restrict__ CTg,
             int N, int K, float alpha,
             size_t strA, size_t strB, size_t strC)
{
    extern __shared__ char dsm[];
    const uint32_t sb = (smem_u32(dsm) + 1023u) & ~1023u;

    Ag += (size_t)blockIdx.z * strA;
    Bg += (size_t)blockIdx.z * strB;
    Cg += (size_t)blockIdx.z * strC;

    const int tid  = threadIdx.x;
    const int lane = tid & 31;
    const int wid  = tid >> 5;           // 0..3
    const int wm0  = (wid & 1) * 64;     // warp m offset
    const int wn0  = (wid >> 1) * 64;    // warp n offset

    int row0, col0;
    if (MODE == 3) {
        const int t = blockIdx.x;
        int r = (int)((sqrtf(8.0f * (float)t + 1.0f) - 1.0f) * 0.5f);
        while ((r + 1) * (r + 2) / 2 <= t) r++;
        while (r * (r + 1) / 2 > t)        r--;
        const int cc = t - r * (r + 1) / 2;
        row0 = r  * 128;
        col0 = cc * 128;
    } else {
        row0 = blockIdx.y * 128;
        col0 = blockIdx.x * 128;
    }

    const int NCH = K >> 5;
    const int q = lane >> 2;             // 0..7 (fragment row)
    const int s = lane & 3;              // 0..3 (fragment k)

    // ldmatrix per-lane row constants: tile = lane>>3, row-in-tile = lane&7
    const uint32_t tb   = ((lane >> 3) & 1) << 3;  // +8 rows for odd tiles
    const uint32_t th16 = ((lane >> 4) & 1) << 4;  // +16B for k-upper tiles
    const uint32_t xr   = (uint32_t)(lane & 7) << 4;  // swizzle term
    uint32_t roffA[4], roffB[4];
#pragma unroll
    for (int t4 = 0; t4 < 4; t4++) {
        roffA[t4] = (uint32_t)(wm0 + (t4 << 4) + tb + (lane & 7)) << 7;
        roffB[t4] = (uint32_t)(wn0 + (t4 << 4) + tb + (lane & 7)) << 7;
    }

    float acc[4][8][4];
#pragma unroll
    for (int i = 0; i < 4; i++)
#pragma unroll
        for (int j = 0; j < 8; j++)
#pragma unroll
            for (int r = 0; r < 4; r++) acc[i][j][r] = 0.f;

    auto issue = [&](int ch, int st) {
        const int k0 = ch << 5;
#pragma unroll
        for (int i = 0; i < 16; i++) {
            int g   = tid + (i << 7);          // 0..2047
            int isB = g >> 10;
            int gl  = g & 1023;
            int r   = gl >> 3;                 // row 0..127
            int gg  = gl & 7;                  // 16B granule
            const float* src = (isB ? Bg + (size_t)(col0 + r) * K
                                    : Ag + (size_t)(row0 + r) * K) + k0 + (gg << 2);
            uint32_t dst = sb + (isB ? SB_OFF : 0) + st * B_TB
                         + sw128((r << 7) + (gg << 4));
            asm volatile("cp.async.cg.shared.global [%0], [%1], 16;"
                         :: "r"(dst), "l"(src) : "memory");
        }
        asm volatile("cp.async.commit_group;" ::: "memory");
    };

    auto step = [&](int ch, const int st) {
        asm volatile("cp.async.wait_group 1;" ::: "memory");
        __syncthreads();
        if (ch + 2 < NCH) issue(ch + 2, (st + 2) % STG);
        else asm volatile("cp.async.commit_group;" ::: "memory");

        const uint32_t ab = sb + st * A_TB;
        const uint32_t bb = sb + SB_OFF + st * B_TB;

#pragma unroll
        for (int ks = 0; ks < 4; ks++) {
            const uint32_t kx = (((uint32_t)ks << 5) + th16) ^ xr;
            uint32_t af[16], bf[16];
#pragma unroll
            for (int tp = 0; tp < 4; tp++) {
                // B tiles: r0 = b0(n-tile 2tp), r1 = b0(2tp+1), r2 = b1(2tp), r3 = b1(2tp+1)
                ldsm4(bb + roffB[tp] + kx,
                      bf[(tp * 2) * 2], bf[(tp * 2 + 1) * 2],
                      bf[(tp * 2) * 2 + 1], bf[(tp * 2 + 1) * 2 + 1]);
            }
#pragma unroll
            for (int tm = 0; tm < 4; tm++)
                ldsm4(ab + roffA[tm] + kx,
                      af[tm * 4], af[tm * 4 + 1], af[tm * 4 + 2], af[tm * 4 + 3]);
#pragma unroll
            for (int tm = 0; tm < 4; tm++)
#pragma unroll
                for (int tn = 0; tn < 8; tn++)
                    mma_tf32(acc[tm][tn], af[tm * 4], af[tm * 4 + 1],
                             af[tm * 4 + 2], af[tm * 4 + 3],
                             bf[tn * 2], bf[tn * 2 + 1]);
        }
    };

    issue(0, 0);
    issue(1, 1);

    int ch = 0;
#pragma unroll 1
    for (; ch + 3 <= NCH; ch += 3) {
        step(ch,     0);
        step(ch + 1, 1);
        step(ch + 2, 2);
    }
    if (ch < NCH) { step(ch, 0); ch++; }
    if (ch < NCH) { step(ch, 1); }

    // -------- epilogue --------
    if (MODE == 0) {
        // bias + tf32 round into acc, write C
#pragma unroll
        for (int tm = 0; tm < 4; tm++) {
            const size_t r_lo = (size_t)row0 + wm0 + (tm << 4) + q;
#pragma unroll
            for (int tn = 0; tn < 8; tn++) {
                const int col = col0 + wn0 + (tn << 3) + (s << 1);
                const float b0 = __ldg(bias + col), b1 = __ldg(bias + col + 1);
                float v0 = rtf(acc[tm][tn][0] + b0);
                float v1 = rtf(acc[tm][tn][1] + b1);
                float v2 = rtf(acc[tm][tn][2] + b0);
                float v3 = rtf(acc[tm][tn][3] + b1);
                acc[tm][tn][0] = v0; acc[tm][tn][1] = v1;
                acc[tm][tn][2] = v2; acc[tm][tn][3] = v3;
                *reinterpret_cast<float2*>(Cg + r_lo * N + col)       = make_float2(v0, v1);
                *reinterpret_cast<float2*>(Cg + (r_lo + 8) * N + col) = make_float2(v2, v3);
            }
        }
        // stage transpose in smem, write C^T coalesced
        asm volatile("cp.async.wait_group 0;" ::: "memory");
        __syncthreads();
#pragma unroll
        for (int tm = 0; tm < 4; tm++) {
            const int m = wm0 + (tm << 4) + q;
#pragma unroll
            for (int tn = 0; tn < 8; tn++) {
                const int n = wn0 + (tn << 3) + (s << 1);
                sts_f(sb + (uint32_t)(n       * TPITCH + m)     * 4, acc[tm][tn][0]);
                sts_f(sb + (uint32_t)((n + 1) * TPITCH + m)     * 4, acc[tm][tn][1]);
                sts_f(sb + (uint32_t)(n       * TPITCH + m + 8) * 4, acc[tm][tn][2]);
                sts_f(sb + (uint32_t)((n + 1) * TPITCH + m + 8) * 4, acc[tm][tn][3]);
            }
        }
        __syncthreads();
        const int b  = row0 >> 11;           // batch (rows are batch-major)
        const int m2 = row0 & 2047;
        float* dstrow = CTg + (size_t)b * OUTD * SEQ + (size_t)(col0 + tid) * SEQ + m2;
        const uint32_t srow = sb + (uint32_t)(tid * TPITCH) * 4;
#pragma unroll
        for (int j = 0; j < 128; j += 4) {
            float4 v = lds_f4(srow + j * 4);
            *reinterpret_cast<float4*>(dstrow + j) = v;
        }
    } else if (MODE == 1) {
#pragma unroll
        for (int tm = 0; tm < 4; tm++) {
            const size_t r_lo = (size_t)row0 + wm0 + (tm << 4) + q;
#pragma unroll
            for (int tn = 0; tn < 8; tn++) {
                const int col = col0 + wn0 + (tn << 3) + (s << 1);
                *reinterpret_cast<float2*>(Cg + r_lo * N + col) =
                    make_float2(acc[tm][tn][0], acc[tm][tn][1]);
                *reinterpret_cast<float2*>(Cg + (r_lo + 8) * N + col) =
                    make_float2(acc[tm][tn][2], acc[tm][tn][3]);
            }
        }
    } else {  // MODE 3
        const bool diag = (row0 == col0);
#pragma unroll
        for (int tm = 0; tm < 4; tm++) {
            const size_t r_lo = (size_t)row0 + wm0 + (tm << 4) + q;
#pragma unroll
            for (int tn = 0; tn < 8; tn++) {
                const int col = col0 + wn0 + (tn << 3) + (s << 1);
                float v0 = acc[tm][tn][0] * alpha, v1 = acc[tm][tn][1] * alpha;
                float v2 = acc[tm][tn][2] * alpha, v3 = acc[tm][tn][3] * alpha;
                acc[tm][tn][0] = v0; acc[tm][tn][1] = v1;
                acc[tm][tn][2] = v2; acc[tm][tn][3] = v3;
                *reinterpret_cast<float2*>(Cg + r_lo * N + col)       = make_float2(v0, v1);
                *reinterpret_cast<float2*>(Cg + (r_lo + 8) * N + col) = make_float2(v2, v3);
            }
        }
        if (!diag) {
            asm volatile("cp.async.wait_group 0;" ::: "memory");
            __syncthreads();
#pragma unroll
            for (int tm = 0; tm < 4; tm++) {
                const int m = wm0 + (tm << 4) + q;
#pragma unroll
                for (int tn = 0; tn < 8; tn++) {
                    const int n = wn0 + (tn << 3) + (s << 1);
                    sts_f(sb + (uint32_t)(n       * TPITCH + m)     * 4, acc[tm][tn][0]);
                    sts_f(sb + (uint32_t)((n + 1) * TPITCH + m)     * 4, acc[tm][tn][1]);
                    sts_f(sb + (uint32_t)(n       * TPITCH + m + 8) * 4, acc[tm][tn][2]);
                    sts_f(sb + (uint32_t)((n + 1) * TPITCH + m + 8) * 4, acc[tm][tn][3]);
                }
            }
            __syncthreads();
            float* dstrow = Cg + (size_t)(col0 + tid) * N + row0;
            const uint32_t srow = sb + (uint32_t)(tid * TPITCH) * 4;
#pragma unroll
            for (int j = 0; j < 128; j += 4) {
                float4 v = lds_f4(srow + j * 4);
                *reinterpret_cast<float4*>(dstrow + j) = v;
            }
        }
    }
}

// ---------------------------------------------------------------------------
__global__ __launch_bounds__(256)
void round_k(const float4* __restrict__ in, float4* __restrict__ out, int n4)
{
    int i = blockIdx.x * 256 + threadIdx.x;
    if (i < n4) {
        float4 v = in[i];
        v.x = rtf(v.x); v.y = rtf(v.y); v.z = rtf(v.z); v.w = rtf(v.w);
        out[i] = v;
    }
}

// row softmax over 2048 cols (float4 vectorized); probs rounded to tf32
__global__ __launch_bounds__(256)
void softmax_kernel(float* __restrict__ S)
{
    float4* p4 = reinterpret_cast<float4*>(S + (size_t)blockIdx.x * SEQ);
    const int tid  = threadIdx.x;
    const int lane = tid & 31;
    const int wid  = tid >> 5;
    __shared__ float red[8];

    float4 u0 = p4[tid], u1 = p4[tid + 256];
    float m = fmaxf(fmaxf(fmaxf(u0.x, u0.y), fmaxf(u0.z, u0.w)),
                    fmaxf(fmaxf(u1.x, u1.y), fmaxf(u1.z, u1.w)));
#pragma unroll
    for (int o = 16; o > 0; o >>= 1)
        m = fmaxf(m, __shfl_xor_sync(0xffffffffu, m, o));
    if (lane == 0) red[wid] = m;
    __syncthreads();
    float bm = red[0];
#pragma unroll
    for (int i = 1; i < 8; i++) bm = fmaxf(bm, red[i]);
    __syncthreads();

    u0.x = __expf(u0.x - bm); u0.y = __expf(u0.y - bm);
    u0.z = __expf(u0.z - bm); u0.w = __expf(u0.w - bm);
    u1.x = __expf(u1.x - bm); u1.y = __expf(u1.y - bm);
    u1.z = __expf(u1.z - bm); u1.w = __expf(u1.w - bm);
    float sum = (u0.x + u0.y) + (u0.z + u0.w) + (u1.x + u1.y) + (u1.z + u1.w);
#pragma unroll
    for (int o = 16; o > 0; o >>= 1)
        sum += __shfl_xor_sync(0xffffffffu, sum, o);
    if (lane == 0) red[wid] = sum;
    __syncthreads();
    float total = 0.f;
#pragma unroll
    for (int i = 0; i < 8; i++) total += red[i];
    const float inv = 1.f / total;

    u0.x = rtf(u0.x * inv); u0.y = rtf(u0.y * inv);
    u0.z = rtf(u0.z * inv); u0.w = rtf(u0.w * inv);
    u1.x = rtf(u1.x * inv); u1.y = rtf(u1.y * inv);
    u1.z = rtf(u1.z * inv); u1.w = rtf(u1.w * inv);
    p4[tid]       = u0;
    p4[tid + 256] = u1;
}

// ---------------------------------------------------------------------------
extern "C" void kernel_launch(void* const* d_in, const int* in_sizes, int n_in,
                              void* d_out, int out_size)
{
    const float* embd = (const float*)d_in[0];   // [8,2048,1024]
    const float* W    = (const float*)d_in[1];   // [1024,1024]
    const float* bias = (const float*)d_in[2];   // [1024]
    float* out = (float*)d_out;                  // [8,2048,1024]

    float *et, *wt, *c, *ct, *s;
    cudaGetSymbolAddress((void**)&et, g_et);
    cudaGetSymbolAddress((void**)&wt, g_wt);
    cudaGetSymbolAddress((void**)&c,  g_c);
    cudaGetSymbolAddress((void**)&ct, g_ct);
    cudaGetSymbolAddress((void**)&s,  g_s);

    cudaFuncSetAttribute(tc_gemm<0>, cudaFuncAttributeMaxDynamicSharedMemorySize, DSMEM);
    cudaFuncSetAttribute(tc_gemm<1>, cudaFuncAttributeMaxDynamicSharedMemorySize, DSMEM);
    cudaFuncSetAttribute(tc_gemm<3>, cudaFuncAttributeMaxDynamicSharedMemorySize, DSMEM);

    const float scale = 0.03125f;  // 1/sqrt(1024)

    // prepass: round inputs to tf32 (unbiased)
    {
        int n4e = BATCH * SEQ * EMBD / 4;
        round_k<<<n4e / 256, 256>>>((const float4*)embd, (float4*)et, n4e);
        int n4w = OUTD * EMBD / 4;
        round_k<<<n4w / 256, 256>>>((const float4*)W, (float4*)wt, n4w);
    }

    // 1) c = embd @ W^T + b  (NT), writes c AND c^T (both tf32-rounded)
    {
        dim3 grid(OUTD / 128, (BATCH * SEQ) / 128, 1);
        tc_gemm<0><<<grid, 128, DSMEM>>>(et, wt, bias, c, ct,
                                         OUTD, EMBD, 1.0f, 0, 0, 0);
    }
    // 2) s = (c @ c^T) * scale per batch — symmetric: 136 triangular tiles
    {
        dim3 grid(136, 1, BATCH);
        tc_gemm<3><<<grid, 128, DSMEM>>>(c, c, nullptr, s, nullptr,
                                         SEQ, OUTD, scale,
                                         (size_t)SEQ * OUTD, (size_t)SEQ * OUTD,
                                         (size_t)SEQ * SEQ);
    }
    // 3) softmax rows (stores tf32-rounded probs)
    softmax_kernel<<<BATCH * SEQ, 256>>>(s);

    // 4) out = P @ c  ==  P @ (c^T)^T  (NT, M=2048, N=1024, K=2048)
    {
        dim3 grid(OUTD / 128, SEQ / 128, BATCH);
        tc_gemm<1><<<grid, 128, DSMEM>>>(s, ct, nullptr, out, nullptr,
                                         OUTD, SEQ, 1.0f,
                                         (size_t)SEQ * SEQ, (size_t)OUTD * SEQ,
                                         (size_t)SEQ * OUTD);
    }
}

// round 8
// speedup vs baseline: 4.8514x; 1.0046x over previous
#include <cuda_runtime.h>
#include <cuda_bf16.h>
#include <cstdint>

#define BATCH 8
#define SEQ   2048
#define EMBD  1024
#define OUTD  1024

// Scratch (device globals; allocations are forbidden)
__device__ __align__(256) float g_et[(size_t)BATCH * SEQ * EMBD];  // tf32 embd  64MB
__device__ __align__(256) float g_wt[(size_t)OUTD * EMBD];         // tf32 W      4MB
__device__ __align__(256) float g_c [(size_t)BATCH * SEQ * OUTD];  // c (tf32)   64MB
__device__ __align__(256) float g_ct[(size_t)BATCH * OUTD * SEQ];  // c^T (tf32) 64MB
__device__ __align__(256) float g_s [(size_t)BATCH * SEQ * SEQ];   // scores    128MB

// ---------------------------------------------------------------------------
__device__ __forceinline__ uint32_t smem_u32(const void* p) {
    uint32_t a;
    asm("{ .reg .u64 t; cvta.to.shared.u64 t, %1; cvt.u32.u64 %0, t; }"
        : "=r"(a) : "l"(p));
    return a;
}
// fp32 -> tf32 round-to-nearest (unbiased)
__device__ __forceinline__ float rtf(float x) {
    uint32_t u;
    asm("cvt.rna.tf32.f32 %0, %1;" : "=r"(u) : "f"(x));
    return __uint_as_float(u);
}
__device__ __forceinline__ void sts_f(uint32_t a, float v) {
    asm volatile("st.shared.b32 [%0], %1;" :: "r"(a), "f"(v) : "memory");
}
__device__ __forceinline__ float4 lds_f4(uint32_t a) {
    float4 v;
    asm volatile("ld.shared.v4.f32 {%0,%1,%2,%3}, [%4];"
                 : "=f"(v.x), "=f"(v.y), "=f"(v.z), "=f"(v.w) : "r"(a));
    return v;
}
// ldmatrix x4: four 8-row x 16B tiles; per-thread row address
__device__ __forceinline__ void ldsm4(uint32_t addr, uint32_t& r0, uint32_t& r1,
                                      uint32_t& r2, uint32_t& r3) {
    asm volatile("ldmatrix.sync.aligned.m8n8.x4.shared.b16 {%0,%1,%2,%3}, [%4];"
                 : "=r"(r0), "=r"(r1), "=r"(r2), "=r"(r3) : "r"(addr));
}
__device__ __forceinline__ void mma_tf32(float c[4], uint32_t a0, uint32_t a1,
                                         uint32_t a2, uint32_t a3,
                                         uint32_t b0, uint32_t b1) {
    asm volatile(
        "mma.sync.aligned.m16n8k8.row.col.f32.tf32.tf32.f32 "
        "{%0,%1,%2,%3}, {%4,%5,%6,%7}, {%8,%9}, {%0,%1,%2,%3};"
        : "+f"(c[0]), "+f"(c[1]), "+f"(c[2]), "+f"(c[3])
        : "r"(a0), "r"(a1), "r"(a2), "r"(a3), "r"(b0), "r"(b1));
}
__device__ __forceinline__ uint32_t sw128(uint32_t bo) {
    return bo ^ ((bo >> 3) & 0x70);
}

// ---------------------------------------------------------------------------
// tf32 mma.sync GEMM (all NT): 128x128 CTA tile, BK=32, 4 warps, warp 64x64.
// ldmatrix.x4 fragments, double-buffered across k-steps (LDS hidden under MMA).
// MODE 0: epilogue = +bias, round->tf32, write C AND C^T  (GEMM1)
// MODE 1: plain                                            (GEMM3)
// MODE 3: *alpha, SYMMETRIC triangular tiles, mirrored     (GEMM2)
// ---------------------------------------------------------------------------
#define STG     3
#define A_TB    16384                    // 128 rows x 128B
#define SB_OFF  (STG * A_TB)             // 49152
#define B_TB    16384
#define DSMEM   (SB_OFF + STG * B_TB + 1024)
#define TPITCH  132                      // transpose staging pitch (floats)

template <int MODE>
__global__ __launch_bounds__(128, 2)
void tc_gemm(const float* __restrict__ Ag, const float* __restrict__ Bg,
             const float* __restrict__ bias, float* __restrict__ Cg,
             float* __restrict__ CTg,
             int N, int K, float alpha,
             size_t strA, size_t strB, size_t strC)
{
    extern __shared__ char dsm[];
    const uint32_t sb = (smem_u32(dsm) + 1023u) & ~1023u;

    Ag += (size_t)blockIdx.z * strA;
    Bg += (size_t)blockIdx.z * strB;
    Cg += (size_t)blockIdx.z * strC;

    const int tid  = threadIdx.x;
    const int lane = tid & 31;
    const int wid  = tid >> 5;           // 0..3
    const int wm0  = (wid & 1) * 64;     // warp m offset
    const int wn0  = (wid >> 1) * 64;    // warp n offset

    int row0, col0;
    if (MODE == 3) {
        const int t = blockIdx.x;
        int r = (int)((sqrtf(8.0f * (float)t + 1.0f) - 1.0f) * 0.5f);
        while ((r + 1) * (r + 2) / 2 <= t) r++;
        while (r * (r + 1) / 2 > t)        r--;
        const int cc = t - r * (r + 1) / 2;
        row0 = r  * 128;
        col0 = cc * 128;
    } else {
        row0 = blockIdx.y * 128;
        col0 = blockIdx.x * 128;
    }

    const int NCH = K >> 5;
    const int q = lane >> 2;             // 0..7 (fragment row)
    const int s = lane & 3;              // 0..3 (fragment k)

    // ldmatrix per-lane row constants
    const uint32_t tb   = ((lane >> 3) & 1) << 3;
    const uint32_t th16 = ((lane >> 4) & 1) << 4;
    const uint32_t xr   = (uint32_t)(lane & 7) << 4;
    uint32_t roffA[4], roffB[4];
#pragma unroll
    for (int t4 = 0; t4 < 4; t4++) {
        roffA[t4] = (uint32_t)(wm0 + (t4 << 4) + tb + (lane & 7)) << 7;
        roffB[t4] = (uint32_t)(wn0 + (t4 << 4) + tb + (lane & 7)) << 7;
    }

    float acc[4][8][4];
#pragma unroll
    for (int i = 0; i < 4; i++)
#pragma unroll
        for (int j = 0; j < 8; j++)
#pragma unroll
            for (int r = 0; r < 4; r++) acc[i][j][r] = 0.f;

    auto issue = [&](int ch, int st) {
        const int k0 = ch << 5;
#pragma unroll
        for (int i = 0; i < 16; i++) {
            int g   = tid + (i << 7);          // 0..2047
            int isB = g >> 10;
            int gl  = g & 1023;
            int r   = gl >> 3;                 // row 0..127
            int gg  = gl & 7;                  // 16B granule
            const float* src = (isB ? Bg + (size_t)(col0 + r) * K
                                    : Ag + (size_t)(row0 + r) * K) + k0 + (gg << 2);
            uint32_t dst = sb + (isB ? SB_OFF : 0) + st * B_TB
                         + sw128((r << 7) + (gg << 4));
            asm volatile("cp.async.cg.shared.global [%0], [%1], 16;"
                         :: "r"(dst), "l"(src) : "memory");
        }
        asm volatile("cp.async.commit_group;" ::: "memory");
    };

    auto ldfrags = [&](uint32_t ab, uint32_t bb, int ks,
                       uint32_t* af, uint32_t* bf) {
        const uint32_t kx = (((uint32_t)ks << 5) + th16) ^ xr;
#pragma unroll
        for (int tp = 0; tp < 4; tp++)
            ldsm4(bb + roffB[tp] + kx,
                  bf[(tp * 2) * 2], bf[(tp * 2 + 1) * 2],
                  bf[(tp * 2) * 2 + 1], bf[(tp * 2 + 1) * 2 + 1]);
#pragma unroll
        for (int tm = 0; tm < 4; tm++)
            ldsm4(ab + roffA[tm] + kx,
                  af[tm * 4], af[tm * 4 + 1], af[tm * 4 + 2], af[tm * 4 + 3]);
    };

    auto step = [&](int ch, const int st) {
        asm volatile("cp.async.wait_group 1;" ::: "memory");
        __syncthreads();
        if (ch + 2 < NCH) issue(ch + 2, (st + 2) % STG);
        else asm volatile("cp.async.commit_group;" ::: "memory");

        const uint32_t ab = sb + st * A_TB;
        const uint32_t bb = sb + SB_OFF + st * B_TB;

        uint32_t af[2][16], bf[2][16];
        ldfrags(ab, bb, 0, af[0], bf[0]);
#pragma unroll
        for (int ks = 0; ks < 4; ks++) {
            if (ks < 3)
                ldfrags(ab, bb, ks + 1, af[(ks + 1) & 1], bf[(ks + 1) & 1]);
            const uint32_t* A = af[ks & 1];
            const uint32_t* B = bf[ks & 1];
#pragma unroll
            for (int tm = 0; tm < 4; tm++)
#pragma unroll
                for (int tn = 0; tn < 8; tn++)
                    mma_tf32(acc[tm][tn], A[tm * 4], A[tm * 4 + 1],
                             A[tm * 4 + 2], A[tm * 4 + 3],
                             B[tn * 2], B[tn * 2 + 1]);
        }
    };

    issue(0, 0);
    issue(1, 1);

    int ch = 0;
#pragma unroll 1
    for (; ch + 3 <= NCH; ch += 3) {
        step(ch,     0);
        step(ch + 1, 1);
        step(ch + 2, 2);
    }
    if (ch < NCH) { step(ch, 0); ch++; }
    if (ch < NCH) { step(ch, 1); }

    // -------- epilogue --------
    if (MODE == 0) {
        // bias + tf32 round into acc, write C
#pragma unroll
        for (int tm = 0; tm < 4; tm++) {
            const size_t r_lo = (size_t)row0 + wm0 + (tm << 4) + q;
#pragma unroll
            for (int tn = 0; tn < 8; tn++) {
                const int col = col0 + wn0 + (tn << 3) + (s << 1);
                const float b0 = __ldg(bias + col), b1 = __ldg(bias + col + 1);
                float v0 = rtf(acc[tm][tn][0] + b0);
                float v1 = rtf(acc[tm][tn][1] + b1);
                float v2 = rtf(acc[tm][tn][2] + b0);
                float v3 = rtf(acc[tm][tn][3] + b1);
                acc[tm][tn][0] = v0; acc[tm][tn][1] = v1;
                acc[tm][tn][2] = v2; acc[tm][tn][3] = v3;
                *reinterpret_cast<float2*>(Cg + r_lo * N + col)       = make_float2(v0, v1);
                *reinterpret_cast<float2*>(Cg + (r_lo + 8) * N + col) = make_float2(v2, v3);
            }
        }
        // stage transpose in smem, write C^T coalesced
        asm volatile("cp.async.wait_group 0;" ::: "memory");
        __syncthreads();
#pragma unroll
        for (int tm = 0; tm < 4; tm++) {
            const int m = wm0 + (tm << 4) + q;
#pragma unroll
            for (int tn = 0; tn < 8; tn++) {
                const int n = wn0 + (tn << 3) + (s << 1);
                sts_f(sb + (uint32_t)(n       * TPITCH + m)     * 4, acc[tm][tn][0]);
                sts_f(sb + (uint32_t)((n + 1) * TPITCH + m)     * 4, acc[tm][tn][1]);
                sts_f(sb + (uint32_t)(n       * TPITCH + m + 8) * 4, acc[tm][tn][2]);
                sts_f(sb + (uint32_t)((n + 1) * TPITCH + m + 8) * 4, acc[tm][tn][3]);
            }
        }
        __syncthreads();
        const int b  = row0 >> 11;           // batch (rows are batch-major)
        const int m2 = row0 & 2047;
        float* dstrow = CTg + (size_t)b * OUTD * SEQ + (size_t)(col0 + tid) * SEQ + m2;
        const uint32_t srow = sb + (uint32_t)(tid * TPITCH) * 4;
#pragma unroll
        for (int j = 0; j < 128; j += 4) {
            float4 v = lds_f4(srow + j * 4);
            *reinterpret_cast<float4*>(dstrow + j) = v;
        }
    } else if (MODE == 1) {
#pragma unroll
        for (int tm = 0; tm < 4; tm++) {
            const size_t r_lo = (size_t)row0 + wm0 + (tm << 4) + q;
#pragma unroll
            for (int tn = 0; tn < 8; tn++) {
                const int col = col0 + wn0 + (tn << 3) + (s << 1);
                *reinterpret_cast<float2*>(Cg + r_lo * N + col) =
                    make_float2(acc[tm][tn][0], acc[tm][tn][1]);
                *reinterpret_cast<float2*>(Cg + (r_lo + 8) * N + col) =
                    make_float2(acc[tm][tn][2], acc[tm][tn][3]);
            }
        }
    } else {  // MODE 3
        const bool diag = (row0 == col0);
#pragma unroll
        for (int tm = 0; tm < 4; tm++) {
            const size_t r_lo = (size_t)row0 + wm0 + (tm << 4) + q;
#pragma unroll
            for (int tn = 0; tn < 8; tn++) {
                const int col = col0 + wn0 + (tn << 3) + (s << 1);
                float v0 = acc[tm][tn][0] * alpha, v1 = acc[tm][tn][1] * alpha;
                float v2 = acc[tm][tn][2] * alpha, v3 = acc[tm][tn][3] * alpha;
                acc[tm][tn][0] = v0; acc[tm][tn][1] = v1;
                acc[tm][tn][2] = v2; acc[tm][tn][3] = v3;
                *reinterpret_cast<float2*>(Cg + r_lo * N + col)       = make_float2(v0, v1);
                *reinterpret_cast<float2*>(Cg + (r_lo + 8) * N + col) = make_float2(v2, v3);
            }
        }
        if (!diag) {
            asm volatile("cp.async.wait_group 0;" ::: "memory");
            __syncthreads();
#pragma unroll
            for (int tm = 0; tm < 4; tm++) {
                const int m = wm0 + (tm << 4) + q;
#pragma unroll
                for (int tn = 0; tn < 8; tn++) {
                    const int n = wn0 + (tn << 3) + (s << 1);
                    sts_f(sb + (uint32_t)(n       * TPITCH + m)     * 4, acc[tm][tn][0]);
                    sts_f(sb + (uint32_t)((n + 1) * TPITCH + m)     * 4, acc[tm][tn][1]);
                    sts_f(sb + (uint32_t)(n       * TPITCH + m + 8) * 4, acc[tm][tn][2]);
                    sts_f(sb + (uint32_t)((n + 1) * TPITCH + m + 8) * 4, acc[tm][tn][3]);
                }
            }
            __syncthreads();
            float* dstrow = Cg + (size_t)(col0 + tid) * N + row0;
            const uint32_t srow = sb + (uint32_t)(tid * TPITCH) * 4;
#pragma unroll
            for (int j = 0; j < 128; j += 4) {
                float4 v = lds_f4(srow + j * 4);
                *reinterpret_cast<float4*>(dstrow + j) = v;
            }
        }
    }
}

// ---------------------------------------------------------------------------
__global__ __launch_bounds__(256)
void round_k(const float4* __restrict__ in, float4* __restrict__ out, int n4)
{
    int i = blockIdx.x * 256 + threadIdx.x;
    if (i < n4) {
        float4 v = in[i];
        v.x = rtf(v.x); v.y = rtf(v.y); v.z = rtf(v.z); v.w = rtf(v.w);
        out[i] = v;
    }
}

// row softmax over 2048 cols (float4 vectorized); probs rounded to tf32
__global__ __launch_bounds__(256)
void softmax_kernel(float* __restrict__ S)
{
    float4* p4 = reinterpret_cast<float4*>(S + (size_t)blockIdx.x * SEQ);
    const int tid  = threadIdx.x;
    const int lane = tid & 31;
    const int wid  = tid >> 5;
    __shared__ float red[8];

    float4 u0 = p4[tid], u1 = p4[tid + 256];
    float m = fmaxf(fmaxf(fmaxf(u0.x, u0.y), fmaxf(u0.z, u0.w)),
                    fmaxf(fmaxf(u1.x, u1.y), fmaxf(u1.z, u1.w)));
#pragma unroll
    for (int o = 16; o > 0; o >>= 1)
        m = fmaxf(m, __shfl_xor_sync(0xffffffffu, m, o));
    if (lane == 0) red[wid] = m;
    __syncthreads();
    float bm = red[0];
#pragma unroll
    for (int i = 1; i < 8; i++) bm = fmaxf(bm, red[i]);
    __syncthreads();

    u0.x = __expf(u0.x - bm); u0.y = __expf(u0.y - bm);
    u0.z = __expf(u0.z - bm); u0.w = __expf(u0.w - bm);
    u1.x = __expf(u1.x - bm); u1.y = __expf(u1.y - bm);
    u1.z = __expf(u1.z - bm); u1.w = __expf(u1.w - bm);
    float sum = (u0.x + u0.y) + (u0.z + u0.w) + (u1.x + u1.y) + (u1.z + u1.w);
#pragma unroll
    for (int o = 16; o > 0; o >>= 1)
        sum += __shfl_xor_sync(0xffffffffu, sum, o);
    if (lane == 0) red[wid] = sum;
    __syncthreads();
    float total = 0.f;
#pragma unroll
    for (int i = 0; i < 8; i++) total += red[i];
    const float inv = 1.f / total;

    u0.x = rtf(u0.x * inv); u0.y = rtf(u0.y * inv);
    u0.z = rtf(u0.z * inv); u0.w = rtf(u0.w * inv);
    u1.x = rtf(u1.x * inv); u1.y = rtf(u1.y * inv);
    u1.z = rtf(u1.z * inv); u1.w = rtf(u1.w * inv);
    p4[tid]       = u0;
    p4[tid + 256] = u1;
}

// ---------------------------------------------------------------------------
extern "C" void kernel_launch(void* const* d_in, const int* in_sizes, int n_in,
                              void* d_out, int out_size)
{
    const float* embd = (const float*)d_in[0];   // [8,2048,1024]
    const float* W    = (const float*)d_in[1];   // [1024,1024]
    const float* bias = (const float*)d_in[2];   // [1024]
    float* out = (float*)d_out;                  // [8,2048,1024]

    float *et, *wt, *c, *ct, *s;
    cudaGetSymbolAddress((void**)&et, g_et);
    cudaGetSymbolAddress((void**)&wt, g_wt);
    cudaGetSymbolAddress((void**)&c,  g_c);
    cudaGetSymbolAddress((void**)&ct, g_ct);
    cudaGetSymbolAddress((void**)&s,  g_s);

    cudaFuncSetAttribute(tc_gemm<0>, cudaFuncAttributeMaxDynamicSharedMemorySize, DSMEM);
    cudaFuncSetAttribute(tc_gemm<1>, cudaFuncAttributeMaxDynamicSharedMemorySize, DSMEM);
    cudaFuncSetAttribute(tc_gemm<3>, cudaFuncAttributeMaxDynamicSharedMemorySize, DSMEM);

    const float scale = 0.03125f;  // 1/sqrt(1024)

    // prepass: round inputs to tf32 (unbiased)
    {
        int n4e = BATCH * SEQ * EMBD / 4;
        round_k<<<n4e / 256, 256>>>((const float4*)embd, (float4*)et, n4e);
        int n4w = OUTD * EMBD / 4;
        round_k<<<n4w / 256, 256>>>((const float4*)W, (float4*)wt, n4w);
    }

    // 1) c = embd @ W^T + b  (NT), writes c AND c^T (both tf32-rounded)
    {
        dim3 grid(OUTD / 128, (BATCH * SEQ) / 128, 1);
        tc_gemm<0><<<grid, 128, DSMEM>>>(et, wt, bias, c, ct,
                                         OUTD, EMBD, 1.0f, 0, 0, 0);
    }
    // 2) s = (c @ c^T) * scale per batch — symmetric: 136 triangular tiles
    {
        dim3 grid(136, 1, BATCH);
        tc_gemm<3><<<grid, 128, DSMEM>>>(c, c, nullptr, s, nullptr,
                                         SEQ, OUTD, scale,
                                         (size_t)SEQ * OUTD, (size_t)SEQ * OUTD,
                                         (size_t)SEQ * SEQ);
    }
    // 3) softmax rows (stores tf32-rounded probs)
    softmax_kernel<<<BATCH * SEQ, 256>>>(s);

    // 4) out = P @ c  ==  P @ (c^T)^T  (NT, M=2048, N=1024, K=2048)
    {
        dim3 grid(OUTD / 128, SEQ / 128, BATCH);
        tc_gemm<1><<<grid, 128, DSMEM>>>(s, ct, nullptr, out, nullptr,
                                         OUTD, SEQ, 1.0f,
                                         (size_t)SEQ * SEQ, (size_t)OUTD * SEQ,
                                         (size_t)SEQ * OUTD);
    }
}

// round 9
// speedup vs baseline: 8.1262x; 1.6750x over previous
#include <cuda_runtime.h>
#include <cuda_fp16.h>
#include <cstdint>

#define BATCH 8
#define SEQ   2048
#define EMBD  1024
#define OUTD  1024

// Scratch (device globals; allocations are forbidden)
__device__ __align__(256) __half g_et[(size_t)BATCH * SEQ * EMBD];  // fp16 embd 32MB
__device__ __align__(256) __half g_wt[(size_t)OUTD * EMBD];         // fp16 W     2MB
__device__ __align__(256) __half g_c [(size_t)BATCH * SEQ * OUTD];  // c fp16    32MB
__device__ __align__(256) __half g_ct[(size_t)BATCH * OUTD * SEQ];  // c^T fp16  32MB
__device__ __align__(256) float  g_s [(size_t)BATCH * SEQ * SEQ];   // scores   128MB
__device__ __align__(256) __half g_p [(size_t)BATCH * SEQ * SEQ];   // probs*1024 64MB

// ---------------------------------------------------------------------------
__device__ __forceinline__ uint32_t smem_u32(const void* p) {
    uint32_t a;
    asm("{ .reg .u64 t; cvta.to.shared.u64 t, %1; cvt.u32.u64 %0, t; }"
        : "=r"(a) : "l"(p));
    return a;
}
__device__ __forceinline__ void sts_f(uint32_t a, float v) {
    asm volatile("st.shared.b32 [%0], %1;" :: "r"(a), "f"(v) : "memory");
}
__device__ __forceinline__ float4 lds_f4(uint32_t a) {
    float4 v;
    asm volatile("ld.shared.v4.f32 {%0,%1,%2,%3}, [%4];"
                 : "=f"(v.x), "=f"(v.y), "=f"(v.z), "=f"(v.w) : "r"(a));
    return v;
}
__device__ __forceinline__ void ldsm4(uint32_t addr, uint32_t& r0, uint32_t& r1,
                                      uint32_t& r2, uint32_t& r3) {
    asm volatile("ldmatrix.sync.aligned.m8n8.x4.shared.b16 {%0,%1,%2,%3}, [%4];"
                 : "=r"(r0), "=r"(r1), "=r"(r2), "=r"(r3) : "r"(addr));
}
// fp16 MMA, fp32 accumulate: m16n8k16
__device__ __forceinline__ void mma_f16(float c[4], uint32_t a0, uint32_t a1,
                                        uint32_t a2, uint32_t a3,
                                        uint32_t b0, uint32_t b1) {
    asm volatile(
        "mma.sync.aligned.m16n8k16.row.col.f32.f16.f16.f32 "
        "{%0,%1,%2,%3}, {%4,%5,%6,%7}, {%8,%9}, {%0,%1,%2,%3};"
        : "+f"(c[0]), "+f"(c[1]), "+f"(c[2]), "+f"(c[3])
        : "r"(a0), "r"(a1), "r"(a2), "r"(a3), "r"(b0), "r"(b1));
}
__device__ __forceinline__ uint32_t sw128(uint32_t bo) {
    return bo ^ ((bo >> 3) & 0x70);
}

// ---------------------------------------------------------------------------
// fp16 mma.sync GEMM (all NT): 128x128 CTA tile, BK=64, 4 warps, warp 64x64.
// Tiles: 128 rows x 128B (64 fp16). Same SW128/ldmatrix addressing as tf32.
// MODE 0: +bias, write C fp16 AND C^T fp16                (GEMM1)
// MODE 1: *alpha, write C fp32                             (GEMM3)
// MODE 3: *alpha, fp32, SYMMETRIC triangular + mirror      (GEMM2)
// ---------------------------------------------------------------------------
#define STG     3
#define A_TB    16384                    // 128 rows x 128B
#define SB_OFF  (STG * A_TB)             // 49152
#define B_TB    16384
#define DSMEM   (SB_OFF + STG * B_TB + 1024)
#define TPITCH  132                      // transpose staging pitch (floats)

template <int MODE>
__global__ __launch_bounds__(128, 2)
void tc_gemm(const __half* __restrict__ Ag, const __half* __restrict__ Bg,
             const float* __restrict__ bias,
             float* __restrict__ Cg,            // fp32 out (MODE 1,3)
             __half* __restrict__ Ch,           // fp16 out (MODE 0)
             __half* __restrict__ CTg,          // fp16 transposed out (MODE 0)
             int N, int K, float alpha,
             size_t strA, size_t strB, size_t strC)
{
    extern __shared__ char dsm[];
    const uint32_t sb = (smem_u32(dsm) + 1023u) & ~1023u;

    Ag += (size_t)blockIdx.z * strA;
    Bg += (size_t)blockIdx.z * strB;
    if (MODE != 0) Cg += (size_t)blockIdx.z * strC;

    const int tid  = threadIdx.x;
    const int lane = tid & 31;
    const int wid  = tid >> 5;           // 0..3
    const int wm0  = (wid & 1) * 64;     // warp m offset
    const int wn0  = (wid >> 1) * 64;    // warp n offset

    int row0, col0;
    if (MODE == 3) {
        const int t = blockIdx.x;
        int r = (int)((sqrtf(8.0f * (float)t + 1.0f) - 1.0f) * 0.5f);
        while ((r + 1) * (r + 2) / 2 <= t) r++;
        while (r * (r + 1) / 2 > t)        r--;
        const int cc = t - r * (r + 1) / 2;
        row0 = r  * 128;
        col0 = cc * 128;
    } else {
        row0 = blockIdx.y * 128;
        col0 = blockIdx.x * 128;
    }

    const int NCH = K >> 6;              // BK = 64 fp16
    const int q = lane >> 2;             // 0..7 (fragment row)
    const int s = lane & 3;              // 0..3

    // ldmatrix per-lane constants (identical byte math to tf32 version)
    const uint32_t tb   = ((lane >> 3) & 1) << 3;   // +8 rows for odd tiles
    const uint32_t th16 = ((lane >> 4) & 1) << 4;   // +16B => k 8..15
    const uint32_t xr   = (uint32_t)(lane & 7) << 4;
    uint32_t roffA[4], roffB[4];
#pragma unroll
    for (int t4 = 0; t4 < 4; t4++) {
        roffA[t4] = (uint32_t)(wm0 + (t4 << 4) + tb + (lane & 7)) << 7;
        roffB[t4] = (uint32_t)(wn0 + (t4 << 4) + tb + (lane & 7)) << 7;
    }

    float acc[4][8][4];
#pragma unroll
    for (int i = 0; i < 4; i++)
#pragma unroll
        for (int j = 0; j < 8; j++)
#pragma unroll
            for (int r = 0; r < 4; r++) acc[i][j][r] = 0.f;

    auto issue = [&](int ch, int st) {
        const int k0 = ch << 6;                    // fp16 elements
#pragma unroll
        for (int i = 0; i < 16; i++) {
            int g   = tid + (i << 7);              // 0..2047
            int isB = g >> 10;
            int gl  = g & 1023;
            int r   = gl >> 3;                     // row 0..127
            int gg  = gl & 7;                      // 16B granule (8 fp16)
            const __half* src = (isB ? Bg + (size_t)(col0 + r) * K
                                     : Ag + (size_t)(row0 + r) * K) + k0 + (gg << 3);
            uint32_t dst = sb + (isB ? SB_OFF : 0) + st * B_TB
                         + sw128((r << 7) + (gg << 4));
            asm volatile("cp.async.cg.shared.global [%0], [%1], 16;"
                         :: "r"(dst), "l"(src) : "memory");
        }
        asm volatile("cp.async.commit_group;" ::: "memory");
    };

    auto step = [&](int ch, const int st) {
        asm volatile("cp.async.wait_group 1;" ::: "memory");
        __syncthreads();
        if (ch + 2 < NCH) issue(ch + 2, (st + 2) % STG);
        else asm volatile("cp.async.commit_group;" ::: "memory");

        const uint32_t ab = sb + st * A_TB;
        const uint32_t bb = sb + SB_OFF + st * B_TB;

#pragma unroll
        for (int ks = 0; ks < 4; ks++) {           // 4 x k16 = BK 64
            const uint32_t kx = (((uint32_t)ks << 5) + th16) ^ xr;
            uint32_t af[16], bf[16];
#pragma unroll
            for (int tp = 0; tp < 4; tp++) {
                // 16 n-rows: r0=(n0-7,k0-7) r1=(n8-15,k0-7) r2=(n0-7,k8-15) r3=(n8-15,k8-15)
                ldsm4(bb + roffB[tp] + kx,
                      bf[(tp * 2) * 2], bf[(tp * 2 + 1) * 2],
                      bf[(tp * 2) * 2 + 1], bf[(tp * 2 + 1) * 2 + 1]);
            }
#pragma unroll
            for (int tm = 0; tm < 4; tm++)
                ldsm4(ab + roffA[tm] + kx,
                      af[tm * 4], af[tm * 4 + 1], af[tm * 4 + 2], af[tm * 4 + 3]);
#pragma unroll
            for (int tm = 0; tm < 4; tm++)
#pragma unroll
                for (int tn = 0; tn < 8; tn++)
                    mma_f16(acc[tm][tn], af[tm * 4], af[tm * 4 + 1],
                            af[tm * 4 + 2], af[tm * 4 + 3],
                            bf[tn * 2], bf[tn * 2 + 1]);
        }
    };

    issue(0, 0);
    issue(1, 1);

    int ch = 0;
#pragma unroll 1
    for (; ch + 3 <= NCH; ch += 3) {
        step(ch,     0);
        step(ch + 1, 1);
        step(ch + 2, 2);
    }
    if (ch < NCH) { step(ch, 0); ch++; }
    if (ch < NCH) { step(ch, 1); }

    // -------- epilogue --------
    if (MODE == 0) {
        // bias add, round to fp16, write C (fp16) and stage for C^T
#pragma unroll
        for (int tm = 0; tm < 4; tm++) {
            const size_t r_lo = (size_t)row0 + wm0 + (tm << 4) + q;
#pragma unroll
            for (int tn = 0; tn < 8; tn++) {
                const int col = col0 + wn0 + (tn << 3) + (s << 1);
                const float b0 = __ldg(bias + col), b1 = __ldg(bias + col + 1);
                __half h0 = __float2half_rn(acc[tm][tn][0] + b0);
                __half h1 = __float2half_rn(acc[tm][tn][1] + b1);
                __half h2 = __float2half_rn(acc[tm][tn][2] + b0);
                __half h3 = __float2half_rn(acc[tm][tn][3] + b1);
                acc[tm][tn][0] = __half2float(h0);
                acc[tm][tn][1] = __half2float(h1);
                acc[tm][tn][2] = __half2float(h2);
                acc[tm][tn][3] = __half2float(h3);
                *reinterpret_cast<__half2*>(Ch + r_lo * N + col) =
                    __halves2half2(h0, h1);
                *reinterpret_cast<__half2*>(Ch + (r_lo + 8) * N + col) =
                    __halves2half2(h2, h3);
            }
        }
        // transpose-stage fp32 in smem, write C^T fp16 coalesced
        asm volatile("cp.async.wait_group 0;" ::: "memory");
        __syncthreads();
#pragma unroll
        for (int tm = 0; tm < 4; tm++) {
            const int m = wm0 + (tm << 4) + q;
#pragma unroll
            for (int tn = 0; tn < 8; tn++) {
                const int n = wn0 + (tn << 3) + (s << 1);
                sts_f(sb + (uint32_t)(n       * TPITCH + m)     * 4, acc[tm][tn][0]);
                sts_f(sb + (uint32_t)((n + 1) * TPITCH + m)     * 4, acc[tm][tn][1]);
                sts_f(sb + (uint32_t)(n       * TPITCH + m + 8) * 4, acc[tm][tn][2]);
                sts_f(sb + (uint32_t)((n + 1) * TPITCH + m + 8) * 4, acc[tm][tn][3]);
            }
        }
        __syncthreads();
        const int b  = row0 >> 11;           // batch (rows are batch-major)
        const int m2 = row0 & 2047;
        __half* dstrow = CTg + (size_t)b * OUTD * SEQ + (size_t)(col0 + tid) * SEQ + m2;
        const uint32_t srow = sb + (uint32_t)(tid * TPITCH) * 4;
#pragma unroll
        for (int j = 0; j < 128; j += 4) {
            float4 v = lds_f4(srow + j * 4);
            *reinterpret_cast<__half2*>(dstrow + j)     = __floats2half2_rn(v.x, v.y);
            *reinterpret_cast<__half2*>(dstrow + j + 2) = __floats2half2_rn(v.z, v.w);
        }
    } else if (MODE == 1) {
#pragma unroll
        for (int tm = 0; tm < 4; tm++) {
            const size_t r_lo = (size_t)row0 + wm0 + (tm << 4) + q;
#pragma unroll
            for (int tn = 0; tn < 8; tn++) {
                const int col = col0 + wn0 + (tn << 3) + (s << 1);
                *reinterpret_cast<float2*>(Cg + r_lo * N + col) =
                    make_float2(acc[tm][tn][0] * alpha, acc[tm][tn][1] * alpha);
                *reinterpret_cast<float2*>(Cg + (r_lo + 8) * N + col) =
                    make_float2(acc[tm][tn][2] * alpha, acc[tm][tn][3] * alpha);
            }
        }
    } else {  // MODE 3
        const bool diag = (row0 == col0);
#pragma unroll
        for (int tm = 0; tm < 4; tm++) {
            const size_t r_lo = (size_t)row0 + wm0 + (tm << 4) + q;
#pragma unroll
            for (int tn = 0; tn < 8; tn++) {
                const int col = col0 + wn0 + (tn << 3) + (s << 1);
                float v0 = acc[tm][tn][0] * alpha, v1 = acc[tm][tn][1] * alpha;
                float v2 = acc[tm][tn][2] * alpha, v3 = acc[tm][tn][3] * alpha;
                acc[tm][tn][0] = v0; acc[tm][tn][1] = v1;
                acc[tm][tn][2] = v2; acc[tm][tn][3] = v3;
                *reinterpret_cast<float2*>(Cg + r_lo * N + col)       = make_float2(v0, v1);
                *reinterpret_cast<float2*>(Cg + (r_lo + 8) * N + col) = make_float2(v2, v3);
            }
        }
        if (!diag) {
            asm volatile("cp.async.wait_group 0;" ::: "memory");
            __syncthreads();
#pragma unroll
            for (int tm = 0; tm < 4; tm++) {
                const int m = wm0 + (tm << 4) + q;
#pragma unroll
                for (int tn = 0; tn < 8; tn++) {
                    const int n = wn0 + (tn << 3) + (s << 1);
                    sts_f(sb + (uint32_t)(n       * TPITCH + m)     * 4, acc[tm][tn][0]);
                    sts_f(sb + (uint32_t)((n + 1) * TPITCH + m)     * 4, acc[tm][tn][1]);
                    sts_f(sb + (uint32_t)(n       * TPITCH + m + 8) * 4, acc[tm][tn][2]);
                    sts_f(sb + (uint32_t)((n + 1) * TPITCH + m + 8) * 4, acc[tm][tn][3]);
                }
            }
            __syncthreads();
            float* dstrow = Cg + (size_t)(col0 + tid) * N + row0;
            const uint32_t srow = sb + (uint32_t)(tid * TPITCH) * 4;
#pragma unroll
            for (int j = 0; j < 128; j += 4) {
                float4 v = lds_f4(srow + j * 4);
                *reinterpret_cast<float4*>(dstrow + j) = v;
            }
        }
    }
}

// ---------------------------------------------------------------------------
// prepass: fp32 -> fp16 (RNE)
__global__ __launch_bounds__(256)
void round_h(const float4* __restrict__ in, __half2* __restrict__ out, int n4)
{
    int i = blockIdx.x * 256 + threadIdx.x;
    if (i < n4) {
        float4 v = in[i];
        out[2 * i]     = __floats2half2_rn(v.x, v.y);
        out[2 * i + 1] = __floats2half2_rn(v.z, v.w);
    }
}

// row softmax over 2048 cols; writes probs*1024 as fp16 (normal range)
__global__ __launch_bounds__(256)
void softmax_kernel(const float* __restrict__ S, __half* __restrict__ P)
{
    const float4* p4 = reinterpret_cast<const float4*>(S + (size_t)blockIdx.x * SEQ);
    __half2* q2 = reinterpret_cast<__half2*>(P + (size_t)blockIdx.x * SEQ);
    const int tid  = threadIdx.x;
    const int lane = tid & 31;
    const int wid  = tid >> 5;
    __shared__ float red[8];

    float4 u0 = p4[tid], u1 = p4[tid + 256];
    float m = fmaxf(fmaxf(fmaxf(u0.x, u0.y), fmaxf(u0.z, u0.w)),
                    fmaxf(fmaxf(u1.x, u1.y), fmaxf(u1.z, u1.w)));
#pragma unroll
    for (int o = 16; o > 0; o >>= 1)
        m = fmaxf(m, __shfl_xor_sync(0xffffffffu, m, o));
    if (lane == 0) red[wid] = m;
    __syncthreads();
    float bm = red[0];
#pragma unroll
    for (int i = 1; i < 8; i++) bm = fmaxf(bm, red[i]);
    __syncthreads();

    u0.x = __expf(u0.x - bm); u0.y = __expf(u0.y - bm);
    u0.z = __expf(u0.z - bm); u0.w = __expf(u0.w - bm);
    u1.x = __expf(u1.x - bm); u1.y = __expf(u1.y - bm);
    u1.z = __expf(u1.z - bm); u1.w = __expf(u1.w - bm);
    float sum = (u0.x + u0.y) + (u0.z + u0.w) + (u1.x + u1.y) + (u1.z + u1.w);
#pragma unroll
    for (int o = 16; o > 0; o >>= 1)
        sum += __shfl_xor_sync(0xffffffffu, sum, o);
    if (lane == 0) red[wid] = sum;
    __syncthreads();
    float total = 0.f;
#pragma unroll
    for (int i = 0; i < 8; i++) total += red[i];
    const float k = 1024.f / total;       // scale by 1024 into fp16 normal range

    q2[2 * tid]           = __floats2half2_rn(u0.x * k, u0.y * k);
    q2[2 * tid + 1]       = __floats2half2_rn(u0.z * k, u0.w * k);
    q2[512 + 2 * tid]     = __floats2half2_rn(u1.x * k, u1.y * k);
    q2[512 + 2 * tid + 1] = __floats2half2_rn(u1.z * k, u1.w * k);
}

// ---------------------------------------------------------------------------
extern "C" void kernel_launch(void* const* d_in, const int* in_sizes, int n_in,
                              void* d_out, int out_size)
{
    const float* embd = (const float*)d_in[0];   // [8,2048,1024]
    const float* W    = (const float*)d_in[1];   // [1024,1024]
    const float* bias = (const float*)d_in[2];   // [1024]
    float* out = (float*)d_out;                  // [8,2048,1024]

    __half *et, *wt, *c, *ct, *p;
    float *s;
    cudaGetSymbolAddress((void**)&et, g_et);
    cudaGetSymbolAddress((void**)&wt, g_wt);
    cudaGetSymbolAddress((void**)&c,  g_c);
    cudaGetSymbolAddress((void**)&ct, g_ct);
    cudaGetSymbolAddress((void**)&s,  g_s);
    cudaGetSymbolAddress((void**)&p,  g_p);

    cudaFuncSetAttribute(tc_gemm<0>, cudaFuncAttributeMaxDynamicSharedMemorySize, DSMEM);
    cudaFuncSetAttribute(tc_gemm<1>, cudaFuncAttributeMaxDynamicSharedMemorySize, DSMEM);
    cudaFuncSetAttribute(tc_gemm<3>, cudaFuncAttributeMaxDynamicSharedMemorySize, DSMEM);

    const float scale = 0.03125f;  // 1/sqrt(1024)

    // prepass: round inputs to fp16
    {
        int n4e = BATCH * SEQ * EMBD / 4;
        round_h<<<n4e / 256, 256>>>((const float4*)embd, (__half2*)et, n4e);
        int n4w = OUTD * EMBD / 4;
        round_h<<<n4w / 256, 256>>>((const float4*)W, (__half2*)wt, n4w);
    }

    // 1) c = embd @ W^T + b  (NT), writes c (fp16) AND c^T (fp16)
    {
        dim3 grid(OUTD / 128, (BATCH * SEQ) / 128, 1);
        tc_gemm<0><<<grid, 128, DSMEM>>>(et, wt, bias, nullptr, c, ct,
                                         OUTD, EMBD, 1.0f, 0, 0, 0);
    }
    // 2) s = (c @ c^T) * scale per batch — symmetric: 136 triangular tiles
    {
        dim3 grid(136, 1, BATCH);
        tc_gemm<3><<<grid, 128, DSMEM>>>(c, c, nullptr, s, nullptr, nullptr,
                                         SEQ, OUTD, scale,
                                         (size_t)SEQ * OUTD, (size_t)SEQ * OUTD,
                                         (size_t)SEQ * SEQ);
    }
    // 3) softmax rows -> probs*1024 in fp16
    softmax_kernel<<<BATCH * SEQ, 256>>>(s, p);

    // 4) out = (P/1024) @ c  ==  P @ (c^T)^T * (1/1024)  (NT)
    {
        dim3 grid(OUTD / 128, SEQ / 128, BATCH);
        tc_gemm<1><<<grid, 128, DSMEM>>>(p, ct, nullptr, out, nullptr, nullptr,
                                         OUTD, SEQ, 1.0f / 1024.f,
                                         (size_t)SEQ * SEQ, (size_t)OUTD * SEQ,
                                         (size_t)SEQ * OUTD);
    }
}